// round 7
// baseline (speedup 1.0000x reference)
#include <cuda_runtime.h>
#include <cstdint>

// SelfAttentionLayer fused kernel, round 4: 512 threads (16 warps) for latency hiding.
// Warp = (row-block, col-slab); weight traffic unchanged, X loads are broadcasts.
//   Q = X Wq + bq ; K = X Wk + bk ; V = X Wv + bv        (X = x[b,h] : [64,256])
//   S[w][v] = sum_c K[w][c] * Q[v][c]   (NO 1/sqrt(d) scale)
//   P = softmax over v ; O = P V ; out = O * X

#define Wn 64
#define Cn 256
#define XS 260   // padded row stride (floats); 260/4=65 odd -> conflict-free row-varying .128
#define SS 68    // padded row stride for the 64x64 score tile

#define SMEM_FLOATS (3 * Wn * XS + Wn * SS)
#define SMEM_BYTES  (SMEM_FLOATS * 4)

#define NTHREADS 512

typedef unsigned long long u64;

#define FMA2(D, A, B, C) \
    asm("fma.rn.f32x2 %0, %1, %2, %3;" : "=l"(D) : "l"(A), "l"(B), "l"(C))
#define ADD2(D, A, B) \
    asm("add.rn.f32x2 %0, %1, %2;" : "=l"(D) : "l"(A), "l"(B))

__device__ __forceinline__ u64 pk2(float lo, float hi) {
    u64 r;
    asm("mov.b64 %0, {%1, %2};" : "=l"(r) : "f"(lo), "f"(hi));
    return r;
}
__device__ __forceinline__ float2 upk2(u64 v) {
    float2 f;
    asm("mov.b64 {%0, %1}, %2;" : "=f"(f.x), "=f"(f.y) : "l"(v));
    return f;
}

// dst[64,256](+pad) = sX @ W + bias. Thread owns rows r0..r0+7, cols [c0, c0+4).
// acc[r] = 2 packed f32x2 pairs (4 channels).
__device__ __forceinline__ void proj_gemm(
    const float* __restrict__ sX, float* __restrict__ dst,
    const float* __restrict__ W, const float* __restrict__ bias,
    int r0, int c0)
{
    u64 acc[8][2];
#pragma unroll
    for (int i = 0; i < 8; i++) { acc[i][0] = 0ULL; acc[i][1] = 0ULL; }

#pragma unroll 2
    for (int k = 0; k < Cn; k += 4) {
        float4 xf[8];
#pragma unroll
        for (int r = 0; r < 8; r++)
            xf[r] = *reinterpret_cast<const float4*>(&sX[(r0 + r) * XS + k]);  // broadcast

        ulonglong2 w[4];   // 16B per lane; warp-contiguous 512B per kk
#pragma unroll
        for (int kk = 0; kk < 4; kk++)
            w[kk] = *reinterpret_cast<const ulonglong2*>(&W[(size_t)(k + kk) * Cn + c0]);

#pragma unroll
        for (int kk = 0; kk < 4; kk++) {
#pragma unroll
            for (int r = 0; r < 8; r++) {
                float xv = (kk == 0) ? xf[r].x : (kk == 1) ? xf[r].y
                         : (kk == 2) ? xf[r].z : xf[r].w;
                u64 xx = pk2(xv, xv);
                FMA2(acc[r][0], xx, w[kk].x, acc[r][0]);
                FMA2(acc[r][1], xx, w[kk].y, acc[r][1]);
            }
        }
    }

    ulonglong2 b = *reinterpret_cast<const ulonglong2*>(&bias[c0]);
#pragma unroll
    for (int r = 0; r < 8; r++) {
        ADD2(acc[r][0], acc[r][0], b.x);
        ADD2(acc[r][1], acc[r][1], b.y);
        ulonglong2 o; o.x = acc[r][0]; o.y = acc[r][1];
        *reinterpret_cast<ulonglong2*>(&dst[(r0 + r) * XS + c0]) = o;
    }
}

__global__ void __launch_bounds__(NTHREADS, 1)
attn_fused_kernel(const float* __restrict__ x,
                  const float* __restrict__ wq, const float* __restrict__ bq,
                  const float* __restrict__ wk, const float* __restrict__ bk,
                  const float* __restrict__ wv, const float* __restrict__ bv,
                  float* __restrict__ out)
{
    extern __shared__ float smem[];
    float* sX  = smem;                 // [64][260] raw input tile (kept for the gate)
    float* sQ  = sX  + Wn * XS;        // [64][260] Q
    float* sKV = sQ  + Wn * XS;        // [64][260] K, later overwritten with V
    float* sS  = sKV + Wn * XS;        // [64][68]  scores -> probabilities

    const int tid = threadIdx.x;
    const size_t bh = blockIdx.x;
    const float* xg = x   + bh * (size_t)(Wn * Cn);
    float*       og = out + bh * (size_t)(Wn * Cn);

    // ---- P0: stage X ----
    for (int i = tid; i < Wn * Cn / 4; i += NTHREADS) {
        int r = i >> 6;
        int c = (i & 63) << 2;
        float4 v = reinterpret_cast<const float4*>(xg)[i];
        *reinterpret_cast<float4*>(&sX[r * XS + c]) = v;
    }
    __syncthreads();

    const int wid  = tid >> 5;          // 0..15
    const int lane = tid & 31;
    const int r0 = (wid >> 1) << 3;     // row block: 8 rows
    const int c0 = ((wid & 1) << 7) + (lane << 2);  // col slab + lane cols

    // ---- P1: Q and K projections ----
    proj_gemm(sX, sQ,  wq, bq, r0, c0);
    proj_gemm(sX, sKV, wk, bk, r0, c0);
    __syncthreads();

    // ---- P2: S = K Q^T ; warp owns 4 q-rows, lane owns k-rows {lane, lane+32} ----
    {
        const int v0 = wid << 2;        // 4 q-rows per warp
        const int w0 = lane;
        u64 a0[4][2], a1[4][2];
#pragma unroll
        for (int j = 0; j < 4; j++) {
            a0[j][0] = a0[j][1] = 0ULL;
            a1[j][0] = a1[j][1] = 0ULL;
        }

#pragma unroll 2
        for (int c = 0; c < Cn; c += 4) {
            ulonglong2 k0 = *reinterpret_cast<const ulonglong2*>(&sKV[w0 * XS + c]);
            ulonglong2 k1 = *reinterpret_cast<const ulonglong2*>(&sKV[(w0 + 32) * XS + c]);
#pragma unroll
            for (int j = 0; j < 4; j++) {
                ulonglong2 q = *reinterpret_cast<const ulonglong2*>(&sQ[(v0 + j) * XS + c]); // broadcast
                FMA2(a0[j][0], k0.x, q.x, a0[j][0]);
                FMA2(a0[j][1], k0.y, q.y, a0[j][1]);
                FMA2(a1[j][0], k1.x, q.x, a1[j][0]);
                FMA2(a1[j][1], k1.y, q.y, a1[j][1]);
            }
        }

        float s0[4], s1[4];
#pragma unroll
        for (int j = 0; j < 4; j++) {
            float2 p00 = upk2(a0[j][0]), p01 = upk2(a0[j][1]);
            float2 p10 = upk2(a1[j][0]), p11 = upk2(a1[j][1]);
            s0[j] = (p00.x + p00.y) + (p01.x + p01.y);
            s1[j] = (p10.x + p10.y) + (p11.x + p11.y);
        }
        *reinterpret_cast<float4*>(&sS[w0 * SS + v0])        = make_float4(s0[0], s0[1], s0[2], s0[3]);
        *reinterpret_cast<float4*>(&sS[(w0 + 32) * SS + v0]) = make_float4(s1[0], s1[1], s1[2], s1[3]);
    }
    __syncthreads();

    // ---- P3: row softmax over v (warp handles rows wid*4 .. wid*4+3) ----
    {
#pragma unroll
        for (int rr = 0; rr < 4; rr++) {
            int r = (wid << 2) + rr;
            float aa = sS[r * SS + lane];
            float bb = sS[r * SS + lane + 32];
            float m = fmaxf(aa, bb);
#pragma unroll
            for (int off = 16; off > 0; off >>= 1)
                m = fmaxf(m, __shfl_xor_sync(0xffffffffu, m, off));
            float e0 = __expf(aa - m);
            float e1 = __expf(bb - m);
            float s = e0 + e1;
#pragma unroll
            for (int off = 16; off > 0; off >>= 1)
                s += __shfl_xor_sync(0xffffffffu, s, off);
            float inv = 1.0f / s;
            sS[r * SS + lane]      = e0 * inv;
            sS[r * SS + lane + 32] = e1 * inv;
        }
    }

    // ---- P4: V projection (overwrites K buffer; P2 reads done before last sync) ----
    proj_gemm(sX, sKV, wv, bv, r0, c0);
    __syncthreads();

    // ---- P5: O = P V (packed along channels), gate with X, store ----
    {
        u64 acc[8][2];
#pragma unroll
        for (int i = 0; i < 8; i++) { acc[i][0] = 0ULL; acc[i][1] = 0ULL; }

#pragma unroll 2
        for (int v = 0; v < Wn; v += 4) {
            float4 pf[8];
#pragma unroll
            for (int r = 0; r < 8; r++)
                pf[r] = *reinterpret_cast<const float4*>(&sS[(r0 + r) * SS + v]); // broadcast

            ulonglong2 va[4];
#pragma unroll
            for (int vv = 0; vv < 4; vv++)
                va[vv] = *reinterpret_cast<const ulonglong2*>(&sKV[(v + vv) * XS + c0]);

#pragma unroll
            for (int vv = 0; vv < 4; vv++) {
#pragma unroll
                for (int r = 0; r < 8; r++) {
                    float p = (vv == 0) ? pf[r].x : (vv == 1) ? pf[r].y
                            : (vv == 2) ? pf[r].z : pf[r].w;
                    u64 pp = pk2(p, p);
                    FMA2(acc[r][0], pp, va[vv].x, acc[r][0]);
                    FMA2(acc[r][1], pp, va[vv].y, acc[r][1]);
                }
            }
        }

#pragma unroll
        for (int r = 0; r < 8; r++) {
            float4 xr = *reinterpret_cast<const float4*>(&sX[(r0 + r) * XS + c0]);
            float2 a0 = upk2(acc[r][0]), a1 = upk2(acc[r][1]);
            float4 o = make_float4(a0.x * xr.x, a0.y * xr.y, a1.x * xr.z, a1.y * xr.w);
            *reinterpret_cast<float4*>(&og[(r0 + r) * Cn + c0]) = o;
        }
    }
}

extern "C" void kernel_launch(void* const* d_in, const int* in_sizes, int n_in,
                              void* d_out, int out_size)
{
    const float* x  = (const float*)d_in[0];
    const float* wq = (const float*)d_in[1];
    const float* bq = (const float*)d_in[2];
    const float* wk = (const float*)d_in[3];
    const float* bk = (const float*)d_in[4];
    const float* wv = (const float*)d_in[5];
    const float* bv = (const float*)d_in[6];
    float* out = (float*)d_out;

    int n_bh = in_sizes[0] / (Wn * Cn);   // B*H = 2048

    cudaFuncSetAttribute(attn_fused_kernel,
                         cudaFuncAttributeMaxDynamicSharedMemorySize, SMEM_BYTES);
    attn_fused_kernel<<<n_bh, NTHREADS, SMEM_BYTES>>>(x, wq, bq, wk, bk, wv, bv, out);
}

// round 8
// speedup vs baseline: 1.0014x; 1.0014x over previous
#include <cuda_runtime.h>
#include <cstdint>

// SelfAttentionLayer fused kernel, round 4: 512 threads (16 warps) for latency hiding.
// Warp = (row-block, col-slab); weight traffic unchanged, X loads are broadcasts.
//   Q = X Wq + bq ; K = X Wk + bk ; V = X Wv + bv        (X = x[b,h] : [64,256])
//   S[w][v] = sum_c K[w][c] * Q[v][c]   (NO 1/sqrt(d) scale)
//   P = softmax over v ; O = P V ; out = O * X

#define Wn 64
#define Cn 256
#define XS 260   // padded row stride (floats); 260/4=65 odd -> conflict-free row-varying .128
#define SS 68    // padded row stride for the 64x64 score tile

#define SMEM_FLOATS (3 * Wn * XS + Wn * SS)
#define SMEM_BYTES  (SMEM_FLOATS * 4)

#define NTHREADS 512

typedef unsigned long long u64;

#define FMA2(D, A, B, C) \
    asm("fma.rn.f32x2 %0, %1, %2, %3;" : "=l"(D) : "l"(A), "l"(B), "l"(C))
#define ADD2(D, A, B) \
    asm("add.rn.f32x2 %0, %1, %2;" : "=l"(D) : "l"(A), "l"(B))

__device__ __forceinline__ u64 pk2(float lo, float hi) {
    u64 r;
    asm("mov.b64 %0, {%1, %2};" : "=l"(r) : "f"(lo), "f"(hi));
    return r;
}
__device__ __forceinline__ float2 upk2(u64 v) {
    float2 f;
    asm("mov.b64 {%0, %1}, %2;" : "=f"(f.x), "=f"(f.y) : "l"(v));
    return f;
}

// dst[64,256](+pad) = sX @ W + bias. Thread owns rows r0..r0+7, cols [c0, c0+4).
// acc[r] = 2 packed f32x2 pairs (4 channels).
__device__ __forceinline__ void proj_gemm(
    const float* __restrict__ sX, float* __restrict__ dst,
    const float* __restrict__ W, const float* __restrict__ bias,
    int r0, int c0)
{
    u64 acc[8][2];
#pragma unroll
    for (int i = 0; i < 8; i++) { acc[i][0] = 0ULL; acc[i][1] = 0ULL; }

#pragma unroll 2
    for (int k = 0; k < Cn; k += 4) {
        float4 xf[8];
#pragma unroll
        for (int r = 0; r < 8; r++)
            xf[r] = *reinterpret_cast<const float4*>(&sX[(r0 + r) * XS + k]);  // broadcast

        ulonglong2 w[4];   // 16B per lane; warp-contiguous 512B per kk
#pragma unroll
        for (int kk = 0; kk < 4; kk++)
            w[kk] = *reinterpret_cast<const ulonglong2*>(&W[(size_t)(k + kk) * Cn + c0]);

#pragma unroll
        for (int kk = 0; kk < 4; kk++) {
#pragma unroll
            for (int r = 0; r < 8; r++) {
                float xv = (kk == 0) ? xf[r].x : (kk == 1) ? xf[r].y
                         : (kk == 2) ? xf[r].z : xf[r].w;
                u64 xx = pk2(xv, xv);
                FMA2(acc[r][0], xx, w[kk].x, acc[r][0]);
                FMA2(acc[r][1], xx, w[kk].y, acc[r][1]);
            }
        }
    }

    ulonglong2 b = *reinterpret_cast<const ulonglong2*>(&bias[c0]);
#pragma unroll
    for (int r = 0; r < 8; r++) {
        ADD2(acc[r][0], acc[r][0], b.x);
        ADD2(acc[r][1], acc[r][1], b.y);
        ulonglong2 o; o.x = acc[r][0]; o.y = acc[r][1];
        *reinterpret_cast<ulonglong2*>(&dst[(r0 + r) * XS + c0]) = o;
    }
}

__global__ void __launch_bounds__(NTHREADS, 1)
attn_fused_kernel(const float* __restrict__ x,
                  const float* __restrict__ wq, const float* __restrict__ bq,
                  const float* __restrict__ wk, const float* __restrict__ bk,
                  const float* __restrict__ wv, const float* __restrict__ bv,
                  float* __restrict__ out)
{
    extern __shared__ float smem[];
    float* sX  = smem;                 // [64][260] raw input tile (kept for the gate)
    float* sQ  = sX  + Wn * XS;        // [64][260] Q
    float* sKV = sQ  + Wn * XS;        // [64][260] K, later overwritten with V
    float* sS  = sKV + Wn * XS;        // [64][68]  scores -> probabilities

    const int tid = threadIdx.x;
    const size_t bh = blockIdx.x;
    const float* xg = x   + bh * (size_t)(Wn * Cn);
    float*       og = out + bh * (size_t)(Wn * Cn);

    // ---- P0: stage X ----
    for (int i = tid; i < Wn * Cn / 4; i += NTHREADS) {
        int r = i >> 6;
        int c = (i & 63) << 2;
        float4 v = reinterpret_cast<const float4*>(xg)[i];
        *reinterpret_cast<float4*>(&sX[r * XS + c]) = v;
    }
    __syncthreads();

    const int wid  = tid >> 5;          // 0..15
    const int lane = tid & 31;
    const int r0 = (wid >> 1) << 3;     // row block: 8 rows
    const int c0 = ((wid & 1) << 7) + (lane << 2);  // col slab + lane cols

    // ---- P1: Q and K projections ----
    proj_gemm(sX, sQ,  wq, bq, r0, c0);
    proj_gemm(sX, sKV, wk, bk, r0, c0);
    __syncthreads();

    // ---- P2: S = K Q^T ; warp owns 4 q-rows, lane owns k-rows {lane, lane+32} ----
    {
        const int v0 = wid << 2;        // 4 q-rows per warp
        const int w0 = lane;
        u64 a0[4][2], a1[4][2];
#pragma unroll
        for (int j = 0; j < 4; j++) {
            a0[j][0] = a0[j][1] = 0ULL;
            a1[j][0] = a1[j][1] = 0ULL;
        }

#pragma unroll 2
        for (int c = 0; c < Cn; c += 4) {
            ulonglong2 k0 = *reinterpret_cast<const ulonglong2*>(&sKV[w0 * XS + c]);
            ulonglong2 k1 = *reinterpret_cast<const ulonglong2*>(&sKV[(w0 + 32) * XS + c]);
#pragma unroll
            for (int j = 0; j < 4; j++) {
                ulonglong2 q = *reinterpret_cast<const ulonglong2*>(&sQ[(v0 + j) * XS + c]); // broadcast
                FMA2(a0[j][0], k0.x, q.x, a0[j][0]);
                FMA2(a0[j][1], k0.y, q.y, a0[j][1]);
                FMA2(a1[j][0], k1.x, q.x, a1[j][0]);
                FMA2(a1[j][1], k1.y, q.y, a1[j][1]);
            }
        }

        float s0[4], s1[4];
#pragma unroll
        for (int j = 0; j < 4; j++) {
            float2 p00 = upk2(a0[j][0]), p01 = upk2(a0[j][1]);
            float2 p10 = upk2(a1[j][0]), p11 = upk2(a1[j][1]);
            s0[j] = (p00.x + p00.y) + (p01.x + p01.y);
            s1[j] = (p10.x + p10.y) + (p11.x + p11.y);
        }
        *reinterpret_cast<float4*>(&sS[w0 * SS + v0])        = make_float4(s0[0], s0[1], s0[2], s0[3]);
        *reinterpret_cast<float4*>(&sS[(w0 + 32) * SS + v0]) = make_float4(s1[0], s1[1], s1[2], s1[3]);
    }
    __syncthreads();

    // ---- P3: row softmax over v (warp handles rows wid*4 .. wid*4+3) ----
    {
#pragma unroll
        for (int rr = 0; rr < 4; rr++) {
            int r = (wid << 2) + rr;
            float aa = sS[r * SS + lane];
            float bb = sS[r * SS + lane + 32];
            float m = fmaxf(aa, bb);
#pragma unroll
            for (int off = 16; off > 0; off >>= 1)
                m = fmaxf(m, __shfl_xor_sync(0xffffffffu, m, off));
            float e0 = __expf(aa - m);
            float e1 = __expf(bb - m);
            float s = e0 + e1;
#pragma unroll
            for (int off = 16; off > 0; off >>= 1)
                s += __shfl_xor_sync(0xffffffffu, s, off);
            float inv = 1.0f / s;
            sS[r * SS + lane]      = e0 * inv;
            sS[r * SS + lane + 32] = e1 * inv;
        }
    }

    // ---- P4: V projection (overwrites K buffer; P2 reads done before last sync) ----
    proj_gemm(sX, sKV, wv, bv, r0, c0);
    __syncthreads();

    // ---- P5: O = P V (packed along channels), gate with X, store ----
    {
        u64 acc[8][2];
#pragma unroll
        for (int i = 0; i < 8; i++) { acc[i][0] = 0ULL; acc[i][1] = 0ULL; }

#pragma unroll 2
        for (int v = 0; v < Wn; v += 4) {
            float4 pf[8];
#pragma unroll
            for (int r = 0; r < 8; r++)
                pf[r] = *reinterpret_cast<const float4*>(&sS[(r0 + r) * SS + v]); // broadcast

            ulonglong2 va[4];
#pragma unroll
            for (int vv = 0; vv < 4; vv++)
                va[vv] = *reinterpret_cast<const ulonglong2*>(&sKV[(v + vv) * XS + c0]);

#pragma unroll
            for (int vv = 0; vv < 4; vv++) {
#pragma unroll
                for (int r = 0; r < 8; r++) {
                    float p = (vv == 0) ? pf[r].x : (vv == 1) ? pf[r].y
                            : (vv == 2) ? pf[r].z : pf[r].w;
                    u64 pp = pk2(p, p);
                    FMA2(acc[r][0], pp, va[vv].x, acc[r][0]);
                    FMA2(acc[r][1], pp, va[vv].y, acc[r][1]);
                }
            }
        }

#pragma unroll
        for (int r = 0; r < 8; r++) {
            float4 xr = *reinterpret_cast<const float4*>(&sX[(r0 + r) * XS + c0]);
            float2 a0 = upk2(acc[r][0]), a1 = upk2(acc[r][1]);
            float4 o = make_float4(a0.x * xr.x, a0.y * xr.y, a1.x * xr.z, a1.y * xr.w);
            *reinterpret_cast<float4*>(&og[(r0 + r) * Cn + c0]) = o;
        }
    }
}

extern "C" void kernel_launch(void* const* d_in, const int* in_sizes, int n_in,
                              void* d_out, int out_size)
{
    const float* x  = (const float*)d_in[0];
    const float* wq = (const float*)d_in[1];
    const float* bq = (const float*)d_in[2];
    const float* wk = (const float*)d_in[3];
    const float* bk = (const float*)d_in[4];
    const float* wv = (const float*)d_in[5];
    const float* bv = (const float*)d_in[6];
    float* out = (float*)d_out;

    int n_bh = in_sizes[0] / (Wn * Cn);   // B*H = 2048

    cudaFuncSetAttribute(attn_fused_kernel,
                         cudaFuncAttributeMaxDynamicSharedMemorySize, SMEM_BYTES);
    attn_fused_kernel<<<n_bh, NTHREADS, SMEM_BYTES>>>(x, wq, bq, wk, bk, wv, bv, out);
}

// round 9
// speedup vs baseline: 1.0512x; 1.0497x over previous
#include <cuda_runtime.h>
#include <cstdint>

// SelfAttentionLayer fused kernel, round 4: 512 threads (16 warps) for latency hiding.
// Warp = (row-block, col-slab); weight traffic unchanged, X loads are broadcasts.
//   Q = X Wq + bq ; K = X Wk + bk ; V = X Wv + bv        (X = x[b,h] : [64,256])
//   S[w][v] = sum_c K[w][c] * Q[v][c]   (NO 1/sqrt(d) scale)
//   P = softmax over v ; O = P V ; out = O * X

#define Wn 64
#define Cn 256
#define XS 260   // padded row stride (floats); 260/4=65 odd -> conflict-free row-varying .128
#define SS 68    // padded row stride for the 64x64 score tile

#define SMEM_FLOATS (3 * Wn * XS + Wn * SS)
#define SMEM_BYTES  (SMEM_FLOATS * 4)

#define NTHREADS 512

typedef unsigned long long u64;

#define FMA2(D, A, B, C) \
    asm("fma.rn.f32x2 %0, %1, %2, %3;" : "=l"(D) : "l"(A), "l"(B), "l"(C))
#define ADD2(D, A, B) \
    asm("add.rn.f32x2 %0, %1, %2;" : "=l"(D) : "l"(A), "l"(B))

__device__ __forceinline__ u64 pk2(float lo, float hi) {
    u64 r;
    asm("mov.b64 %0, {%1, %2};" : "=l"(r) : "f"(lo), "f"(hi));
    return r;
}
__device__ __forceinline__ float2 upk2(u64 v) {
    float2 f;
    asm("mov.b64 {%0, %1}, %2;" : "=f"(f.x), "=f"(f.y) : "l"(v));
    return f;
}

// dst[64,256](+pad) = sX @ W + bias. Thread owns rows r0..r0+7, cols [c0, c0+4).
// acc[r] = 2 packed f32x2 pairs (4 channels).
__device__ __forceinline__ void proj_gemm(
    const float* __restrict__ sX, float* __restrict__ dst,
    const float* __restrict__ W, const float* __restrict__ bias,
    int r0, int c0)
{
    u64 acc[8][2];
#pragma unroll
    for (int i = 0; i < 8; i++) { acc[i][0] = 0ULL; acc[i][1] = 0ULL; }

#pragma unroll 2
    for (int k = 0; k < Cn; k += 4) {
        float4 xf[8];
#pragma unroll
        for (int r = 0; r < 8; r++)
            xf[r] = *reinterpret_cast<const float4*>(&sX[(r0 + r) * XS + k]);  // broadcast

        ulonglong2 w[4];   // 16B per lane; warp-contiguous 512B per kk
#pragma unroll
        for (int kk = 0; kk < 4; kk++)
            w[kk] = *reinterpret_cast<const ulonglong2*>(&W[(size_t)(k + kk) * Cn + c0]);

#pragma unroll
        for (int kk = 0; kk < 4; kk++) {
#pragma unroll
            for (int r = 0; r < 8; r++) {
                float xv = (kk == 0) ? xf[r].x : (kk == 1) ? xf[r].y
                         : (kk == 2) ? xf[r].z : xf[r].w;
                u64 xx = pk2(xv, xv);
                FMA2(acc[r][0], xx, w[kk].x, acc[r][0]);
                FMA2(acc[r][1], xx, w[kk].y, acc[r][1]);
            }
        }
    }

    ulonglong2 b = *reinterpret_cast<const ulonglong2*>(&bias[c0]);
#pragma unroll
    for (int r = 0; r < 8; r++) {
        ADD2(acc[r][0], acc[r][0], b.x);
        ADD2(acc[r][1], acc[r][1], b.y);
        ulonglong2 o; o.x = acc[r][0]; o.y = acc[r][1];
        *reinterpret_cast<ulonglong2*>(&dst[(r0 + r) * XS + c0]) = o;
    }
}

__global__ void __launch_bounds__(NTHREADS, 1)
attn_fused_kernel(const float* __restrict__ x,
                  const float* __restrict__ wq, const float* __restrict__ bq,
                  const float* __restrict__ wk, const float* __restrict__ bk,
                  const float* __restrict__ wv, const float* __restrict__ bv,
                  float* __restrict__ out)
{
    extern __shared__ float smem[];
    float* sX  = smem;                 // [64][260] raw input tile (kept for the gate)
    float* sQ  = sX  + Wn * XS;        // [64][260] Q
    float* sKV = sQ  + Wn * XS;        // [64][260] K, later overwritten with V
    float* sS  = sKV + Wn * XS;        // [64][68]  scores -> probabilities

    const int tid = threadIdx.x;
    const size_t bh = blockIdx.x;
    const float* xg = x   + bh * (size_t)(Wn * Cn);
    float*       og = out + bh * (size_t)(Wn * Cn);

    // ---- P0: stage X ----
    for (int i = tid; i < Wn * Cn / 4; i += NTHREADS) {
        int r = i >> 6;
        int c = (i & 63) << 2;
        float4 v = reinterpret_cast<const float4*>(xg)[i];
        *reinterpret_cast<float4*>(&sX[r * XS + c]) = v;
    }
    __syncthreads();

    const int wid  = tid >> 5;          // 0..15
    const int lane = tid & 31;
    const int r0 = (wid >> 1) << 3;     // row block: 8 rows
    const int c0 = ((wid & 1) << 7) + (lane << 2);  // col slab + lane cols

    // ---- P1: Q and K projections ----
    proj_gemm(sX, sQ,  wq, bq, r0, c0);
    proj_gemm(sX, sKV, wk, bk, r0, c0);
    __syncthreads();

    // ---- P2: S = K Q^T ; warp owns 4 q-rows, lane owns k-rows {lane, lane+32} ----
    {
        const int v0 = wid << 2;        // 4 q-rows per warp
        const int w0 = lane;
        u64 a0[4][2], a1[4][2];
#pragma unroll
        for (int j = 0; j < 4; j++) {
            a0[j][0] = a0[j][1] = 0ULL;
            a1[j][0] = a1[j][1] = 0ULL;
        }

#pragma unroll 2
        for (int c = 0; c < Cn; c += 4) {
            ulonglong2 k0 = *reinterpret_cast<const ulonglong2*>(&sKV[w0 * XS + c]);
            ulonglong2 k1 = *reinterpret_cast<const ulonglong2*>(&sKV[(w0 + 32) * XS + c]);
#pragma unroll
            for (int j = 0; j < 4; j++) {
                ulonglong2 q = *reinterpret_cast<const ulonglong2*>(&sQ[(v0 + j) * XS + c]); // broadcast
                FMA2(a0[j][0], k0.x, q.x, a0[j][0]);
                FMA2(a0[j][1], k0.y, q.y, a0[j][1]);
                FMA2(a1[j][0], k1.x, q.x, a1[j][0]);
                FMA2(a1[j][1], k1.y, q.y, a1[j][1]);
            }
        }

        float s0[4], s1[4];
#pragma unroll
        for (int j = 0; j < 4; j++) {
            float2 p00 = upk2(a0[j][0]), p01 = upk2(a0[j][1]);
            float2 p10 = upk2(a1[j][0]), p11 = upk2(a1[j][1]);
            s0[j] = (p00.x + p00.y) + (p01.x + p01.y);
            s1[j] = (p10.x + p10.y) + (p11.x + p11.y);
        }
        *reinterpret_cast<float4*>(&sS[w0 * SS + v0])        = make_float4(s0[0], s0[1], s0[2], s0[3]);
        *reinterpret_cast<float4*>(&sS[(w0 + 32) * SS + v0]) = make_float4(s1[0], s1[1], s1[2], s1[3]);
    }
    __syncthreads();

    // ---- P3: row softmax over v (warp handles rows wid*4 .. wid*4+3) ----
    {
#pragma unroll
        for (int rr = 0; rr < 4; rr++) {
            int r = (wid << 2) + rr;
            float aa = sS[r * SS + lane];
            float bb = sS[r * SS + lane + 32];
            float m = fmaxf(aa, bb);
#pragma unroll
            for (int off = 16; off > 0; off >>= 1)
                m = fmaxf(m, __shfl_xor_sync(0xffffffffu, m, off));
            float e0 = __expf(aa - m);
            float e1 = __expf(bb - m);
            float s = e0 + e1;
#pragma unroll
            for (int off = 16; off > 0; off >>= 1)
                s += __shfl_xor_sync(0xffffffffu, s, off);
            float inv = 1.0f / s;
            sS[r * SS + lane]      = e0 * inv;
            sS[r * SS + lane + 32] = e1 * inv;
        }
    }

    // ---- P4: V projection (overwrites K buffer; P2 reads done before last sync) ----
    proj_gemm(sX, sKV, wv, bv, r0, c0);
    __syncthreads();

    // ---- P5: O = P V (packed along channels), gate with X, store ----
    {
        u64 acc[8][2];
#pragma unroll
        for (int i = 0; i < 8; i++) { acc[i][0] = 0ULL; acc[i][1] = 0ULL; }

#pragma unroll 2
        for (int v = 0; v < Wn; v += 4) {
            float4 pf[8];
#pragma unroll
            for (int r = 0; r < 8; r++)
                pf[r] = *reinterpret_cast<const float4*>(&sS[(r0 + r) * SS + v]); // broadcast

            ulonglong2 va[4];
#pragma unroll
            for (int vv = 0; vv < 4; vv++)
                va[vv] = *reinterpret_cast<const ulonglong2*>(&sKV[(v + vv) * XS + c0]);

#pragma unroll
            for (int vv = 0; vv < 4; vv++) {
#pragma unroll
                for (int r = 0; r < 8; r++) {
                    float p = (vv == 0) ? pf[r].x : (vv == 1) ? pf[r].y
                            : (vv == 2) ? pf[r].z : pf[r].w;
                    u64 pp = pk2(p, p);
                    FMA2(acc[r][0], pp, va[vv].x, acc[r][0]);
                    FMA2(acc[r][1], pp, va[vv].y, acc[r][1]);
                }
            }
        }

#pragma unroll
        for (int r = 0; r < 8; r++) {
            float4 xr = *reinterpret_cast<const float4*>(&sX[(r0 + r) * XS + c0]);
            float2 a0 = upk2(acc[r][0]), a1 = upk2(acc[r][1]);
            float4 o = make_float4(a0.x * xr.x, a0.y * xr.y, a1.x * xr.z, a1.y * xr.w);
            *reinterpret_cast<float4*>(&og[(r0 + r) * Cn + c0]) = o;
        }
    }
}

extern "C" void kernel_launch(void* const* d_in, const int* in_sizes, int n_in,
                              void* d_out, int out_size)
{
    const float* x  = (const float*)d_in[0];
    const float* wq = (const float*)d_in[1];
    const float* bq = (const float*)d_in[2];
    const float* wk = (const float*)d_in[3];
    const float* bk = (const float*)d_in[4];
    const float* wv = (const float*)d_in[5];
    const float* bv = (const float*)d_in[6];
    float* out = (float*)d_out;

    int n_bh = in_sizes[0] / (Wn * Cn);   // B*H = 2048

    cudaFuncSetAttribute(attn_fused_kernel,
                         cudaFuncAttributeMaxDynamicSharedMemorySize, SMEM_BYTES);
    attn_fused_kernel<<<n_bh, NTHREADS, SMEM_BYTES>>>(x, wq, bq, wk, bk, wv, bv, out);
}

// round 11
// speedup vs baseline: 2.0426x; 1.9431x over previous
#include <cuda_runtime.h>
#include <cuda_bf16.h>
#include <cstdint>

typedef uint32_t u32;

// Pre-split transposed weights: Wt[n][k] bf16 hi/lo, plain row-major [256][256].
__device__ __align__(16) unsigned char g_Wh[3][131072];
__device__ __align__(16) unsigned char g_Wl[3][131072];

// ---- smem byte map ----
#define XHI_B 0                      // X hi [128][264] bf16
#define XLO_B 67584                  // X lo
#define W_B   135168                 // W chunk [64][264] bf16 (hi OR lo per pass)
#define QHI_B 168960                 // Q chunk [128][72] bf16 hi   (phase B: Vt hi [64][136])
#define QLO_B 187392                 // Q lo                        (phase B: Vt lo)
#define VHI_B QHI_B
#define VLO_B (QHI_B + 17408)
#define SMEM_B 205824

#define MMA(d, a0, a1, a2, a3, b0, b1) \
    asm volatile("mma.sync.aligned.m16n8k16.row.col.f32.bf16.bf16.f32 " \
        "{%0,%1,%2,%3},{%4,%5,%6,%7},{%8,%9},{%0,%1,%2,%3};" \
        : "+f"((d)[0]), "+f"((d)[1]), "+f"((d)[2]), "+f"((d)[3]) \
        : "r"(a0), "r"(a1), "r"(a2), "r"(a3), "r"(b0), "r"(b1))

// pack (f0,f1) -> bf16x2 hi word + bf16x2 residual word (lo half = f0)
__device__ __forceinline__ void split2(float f0, float f1, u32& hp, u32& lp) {
    asm("cvt.rn.bf16x2.f32 %0, %1, %2;" : "=r"(hp) : "f"(f1), "f"(f0));
    float h0 = __uint_as_float(hp << 16);
    float h1 = __uint_as_float(hp & 0xffff0000u);
    asm("cvt.rn.bf16x2.f32 %0, %1, %2;" : "=r"(lp) : "f"(f1 - h1), "f"(f0 - h0));
}

// ---------------- prep: transpose + split weights ----------------
__global__ void prep_w(const float* __restrict__ wq, const float* __restrict__ wk,
                       const float* __restrict__ wv)
{
    int idx = blockIdx.x * blockDim.x + threadIdx.x;
    if (idx >= 3 * 65536) return;
    int w = idx >> 16, e = idx & 65535;
    int k = e >> 8, n = e & 255;
    const float* W = (w == 0) ? wq : (w == 1) ? wk : wv;
    float f = W[k * 256 + n];
    __nv_bfloat16 h = __float2bfloat16(f);
    __nv_bfloat16 l = __float2bfloat16(f - __bfloat162float(h));
    *(__nv_bfloat16*)(g_Wh[w] + n * 512 + k * 2) = h;   // Wt[n][k]
    *(__nv_bfloat16*)(g_Wl[w] + n * 512 + k * 2) = l;
}

// copy one W chunk [64 rows x 512B] global -> smem [64 x 528B padded]
__device__ __forceinline__ void copyW(const unsigned char* g, char* smw, int tid) {
    for (int i = tid; i < 2048; i += 256) {
        int r = i >> 5, c = i & 31;
        *(uint4*)(smw + r * 528 + c * 16) = *(const uint4*)(g + r * 512 + c * 16);
    }
}

// projection pass over k=256: warp's 16 rows x 64 chunk cols.
// both=1: acc += Ahi*B + Alo*B (B buffer holds Whi); both=0: acc += Ahi*B (B = Wlo)
__device__ __forceinline__ void proj_pass(const u32* xh, const u32* xl, const u32* ww,
                                          int R, int qd, int tq, float acc[8][4], int both)
{
#pragma unroll 4
    for (int kk = 0; kk < 16; kk++) {
        int cw = kk * 8 + tq;                 // word offset of k-pair
        int i0 = (R + qd) * 132 + cw;
        int i1 = i0 + 8 * 132;
        u32 ah0 = xh[i0], ah1 = xh[i1], ah2 = xh[i0 + 4], ah3 = xh[i1 + 4];
        u32 al0 = 0, al1 = 0, al2 = 0, al3 = 0;
        if (both) { al0 = xl[i0]; al1 = xl[i1]; al2 = xl[i0 + 4]; al3 = xl[i1 + 4]; }
#pragma unroll
        for (int j = 0; j < 8; j++) {
            int bi = (8 * j + qd) * 132 + cw;
            u32 b0 = ww[bi], b1 = ww[bi + 4];
            MMA(acc[j], ah0, ah1, ah2, ah3, b0, b1);
            if (both) MMA(acc[j], al0, al1, al2, al3, b0, b1);
        }
    }
}

__global__ void __launch_bounds__(256, 1)
attn_mma_kernel(const float* __restrict__ x,
                const float* __restrict__ bq, const float* __restrict__ bk,
                const float* __restrict__ bv, float* __restrict__ out)
{
    extern __shared__ char smc[];
    const int tid = threadIdx.x;
    const int w = tid >> 5, t = tid & 31;
    const int qd = t >> 2, tq = t & 3;
    const int R = w * 16;                 // warp's 16 stacked rows
    const int bh64 = (w >> 2) * 64;       // 0 (bh0) or 64 (bh1)

    const float* xg = x + (size_t)blockIdx.x * 32768;
    float*       og = out + (size_t)blockIdx.x * 32768;

    const u32* xh = (const u32*)(smc + XHI_B);
    const u32* xl = (const u32*)(smc + XLO_B);
    const u32* ww = (const u32*)(smc + W_B);
    u32* qh = (u32*)(smc + QHI_B);
    u32* ql = (u32*)(smc + QLO_B);

    // ---- stage X hi/lo ----
    {
        int row = tid >> 1, kh = (tid & 1) * 128;
        const float4* src = (const float4*)(xg + row * 256 + kh);
        u32* dh = (u32*)(smc + XHI_B);
        u32* dl = (u32*)(smc + XLO_B);
        int base = row * 132 + (kh >> 1);
#pragma unroll 8
        for (int j2 = 0; j2 < 32; j2++) {
            float4 v = src[j2];
            u32 h0, l0, h1, l1;
            split2(v.x, v.y, h0, l0);
            split2(v.z, v.w, h1, l1);
            dh[base + 2 * j2] = h0; dh[base + 2 * j2 + 1] = h1;
            dl[base + 2 * j2] = l0; dl[base + 2 * j2 + 1] = l1;
        }
    }

    float S[8][4];
#pragma unroll
    for (int j = 0; j < 8; j++) { S[j][0] = S[j][1] = S[j][2] = S[j][3] = 0.f; }

    // ================= phase A: Q,K proj + S accumulation =================
    for (int cc = 0; cc < 4; cc++) {
        float acc[8][4];
        u32 khi[16], klo[16];
        // ---- Q projection ----
        __syncthreads();
        copyW(g_Wh[0] + cc * 32768, smc + W_B, tid);
        __syncthreads();
#pragma unroll
        for (int j = 0; j < 8; j++) { acc[j][0] = acc[j][1] = acc[j][2] = acc[j][3] = 0.f; }
        proj_pass(xh, xl, ww, R, qd, tq, acc, 1);
        __syncthreads();
        copyW(g_Wl[0] + cc * 32768, smc + W_B, tid);
        __syncthreads();
        proj_pass(xh, xl, ww, R, qd, tq, acc, 0);
        {   // Q epilogue: +bias, split, store to smem [v][72]
            const float* bias = bq + cc * 64;
#pragma unroll
            for (int j = 0; j < 8; j++) {
                float2 bb = *(const float2*)(bias + 8 * j + tq * 2);
                int idx = (R + qd) * 36 + 4 * j + tq;
                u32 hp, lp;
                split2(acc[j][0] + bb.x, acc[j][1] + bb.y, hp, lp);
                qh[idx] = hp; ql[idx] = lp;
                split2(acc[j][2] + bb.x, acc[j][3] + bb.y, hp, lp);
                qh[idx + 288] = hp; ql[idx + 288] = lp;   // row+8
            }
        }
        // ---- K projection (stays in registers) ----
        __syncthreads();
        copyW(g_Wh[1] + cc * 32768, smc + W_B, tid);
        __syncthreads();
#pragma unroll
        for (int j = 0; j < 8; j++) { acc[j][0] = acc[j][1] = acc[j][2] = acc[j][3] = 0.f; }
        proj_pass(xh, xl, ww, R, qd, tq, acc, 1);
        __syncthreads();
        copyW(g_Wl[1] + cc * 32768, smc + W_B, tid);
        __syncthreads();
        proj_pass(xh, xl, ww, R, qd, tq, acc, 0);
        {
            const float* bias = bk + cc * 64;
#pragma unroll
            for (int j = 0; j < 8; j++) {
                float2 bb = *(const float2*)(bias + 8 * j + tq * 2);
                split2(acc[j][0] + bb.x, acc[j][1] + bb.y, khi[2 * j], klo[2 * j]);
                split2(acc[j][2] + bb.x, acc[j][3] + bb.y, khi[2 * j + 1], klo[2 * j + 1]);
            }
        }
        // ---- S += Kc * Qc^T  (A = K regs, B = Q smem; block-diagonal by bh) ----
#pragma unroll
        for (int kk = 0; kk < 4; kk++) {
#pragma unroll
            for (int j = 0; j < 8; j++) {
                int bi = (bh64 + 8 * j + qd) * 36 + kk * 8 + tq;
                u32 b0 = qh[bi], b1 = qh[bi + 4];
                u32 c0 = ql[bi], c1 = ql[bi + 4];
                MMA(S[j], khi[4 * kk], khi[4 * kk + 1], khi[4 * kk + 2], khi[4 * kk + 3], b0, b1);
                MMA(S[j], khi[4 * kk], khi[4 * kk + 1], khi[4 * kk + 2], khi[4 * kk + 3], c0, c1);
                MMA(S[j], klo[4 * kk], klo[4 * kk + 1], klo[4 * kk + 2], klo[4 * kk + 3], b0, b1);
            }
        }
    }

    // ================= softmax on S fragments (in registers) =================
    u32 phi[16], plo[16];
    {
        float m0 = -1e30f, m1 = -1e30f;
#pragma unroll
        for (int j = 0; j < 8; j++) {
            m0 = fmaxf(m0, fmaxf(S[j][0], S[j][1]));
            m1 = fmaxf(m1, fmaxf(S[j][2], S[j][3]));
        }
        m0 = fmaxf(m0, __shfl_xor_sync(0xffffffffu, m0, 1));
        m0 = fmaxf(m0, __shfl_xor_sync(0xffffffffu, m0, 2));
        m1 = fmaxf(m1, __shfl_xor_sync(0xffffffffu, m1, 1));
        m1 = fmaxf(m1, __shfl_xor_sync(0xffffffffu, m1, 2));
        float s0 = 0.f, s1 = 0.f;
#pragma unroll
        for (int j = 0; j < 8; j++) {
            S[j][0] = __expf(S[j][0] - m0); S[j][1] = __expf(S[j][1] - m0);
            S[j][2] = __expf(S[j][2] - m1); S[j][3] = __expf(S[j][3] - m1);
            s0 += S[j][0] + S[j][1];
            s1 += S[j][2] + S[j][3];
        }
        s0 += __shfl_xor_sync(0xffffffffu, s0, 1);
        s0 += __shfl_xor_sync(0xffffffffu, s0, 2);
        s1 += __shfl_xor_sync(0xffffffffu, s1, 1);
        s1 += __shfl_xor_sync(0xffffffffu, s1, 2);
        float i0 = 1.f / s0, i1 = 1.f / s1;
#pragma unroll
        for (int j = 0; j < 8; j++) {
            split2(S[j][0] * i0, S[j][1] * i0, phi[2 * j], plo[2 * j]);
            split2(S[j][2] * i1, S[j][3] * i1, phi[2 * j + 1], plo[2 * j + 1]);
        }
    }

    // ================= phase B: V proj + O = P V + gate =================
    const u32* vhw = (const u32*)(smc + VHI_B);
    const u32* vlw = (const u32*)(smc + VLO_B);
    for (int cc = 0; cc < 4; cc++) {
        float acc[8][4];
        __syncthreads();
        copyW(g_Wh[2] + cc * 32768, smc + W_B, tid);
        __syncthreads();
#pragma unroll
        for (int j = 0; j < 8; j++) { acc[j][0] = acc[j][1] = acc[j][2] = acc[j][3] = 0.f; }
        proj_pass(xh, xl, ww, R, qd, tq, acc, 1);
        __syncthreads();
        copyW(g_Wl[2] + cc * 32768, smc + W_B, tid);
        __syncthreads();
        proj_pass(xh, xl, ww, R, qd, tq, acc, 0);
        {   // V epilogue: +bias, split, transposed store Vt[c][v]
            __nv_bfloat16* vth = (__nv_bfloat16*)(smc + VHI_B);
            __nv_bfloat16* vtl = (__nv_bfloat16*)(smc + VLO_B);
            const float* bias = bv + cc * 64;
            int v0 = R + qd;
#pragma unroll
            for (int j = 0; j < 8; j++) {
                float2 bb = *(const float2*)(bias + 8 * j + tq * 2);
                int c0 = 8 * j + tq * 2;
                float f0 = acc[j][0] + bb.x, f1 = acc[j][1] + bb.y;
                float f2 = acc[j][2] + bb.x, f3 = acc[j][3] + bb.y;
                __nv_bfloat16 h;
                h = __float2bfloat16(f0); vth[c0 * 136 + v0] = h;
                vtl[c0 * 136 + v0] = __float2bfloat16(f0 - __bfloat162float(h));
                h = __float2bfloat16(f1); vth[(c0 + 1) * 136 + v0] = h;
                vtl[(c0 + 1) * 136 + v0] = __float2bfloat16(f1 - __bfloat162float(h));
                h = __float2bfloat16(f2); vth[c0 * 136 + v0 + 8] = h;
                vtl[c0 * 136 + v0 + 8] = __float2bfloat16(f2 - __bfloat162float(h));
                h = __float2bfloat16(f3); vth[(c0 + 1) * 136 + v0 + 8] = h;
                vtl[(c0 + 1) * 136 + v0 + 8] = __float2bfloat16(f3 - __bfloat162float(h));
            }
        }
        __syncthreads();
        // ---- O = P * Vc (A = P regs, B = Vt smem) ----
        float O[8][4];
#pragma unroll
        for (int j = 0; j < 8; j++) { O[j][0] = O[j][1] = O[j][2] = O[j][3] = 0.f; }
#pragma unroll
        for (int kkv = 0; kkv < 4; kkv++) {
#pragma unroll
            for (int j = 0; j < 8; j++) {
                int bi = (8 * j + qd) * 68 + (bh64 >> 1) + kkv * 8 + tq;
                u32 b0 = vhw[bi], b1 = vhw[bi + 4];
                u32 c0 = vlw[bi], c1 = vlw[bi + 4];
                MMA(O[j], phi[4 * kkv], phi[4 * kkv + 1], phi[4 * kkv + 2], phi[4 * kkv + 3], b0, b1);
                MMA(O[j], phi[4 * kkv], phi[4 * kkv + 1], phi[4 * kkv + 2], phi[4 * kkv + 3], c0, c1);
                MMA(O[j], plo[4 * kkv], plo[4 * kkv + 1], plo[4 * kkv + 2], plo[4 * kkv + 3], b0, b1);
            }
        }
        // ---- gate with x, store ----
        {
            int r0 = R + qd;
#pragma unroll
            for (int j = 0; j < 8; j++) {
                int col = cc * 64 + 8 * j + tq * 2;
                float2 x0 = *(const float2*)(xg + r0 * 256 + col);
                float2 x1 = *(const float2*)(xg + (r0 + 8) * 256 + col);
                float2 o0 = make_float2(O[j][0] * x0.x, O[j][1] * x0.y);
                float2 o1 = make_float2(O[j][2] * x1.x, O[j][3] * x1.y);
                *(float2*)(og + r0 * 256 + col) = o0;
                *(float2*)(og + (r0 + 8) * 256 + col) = o1;
            }
        }
    }
}

extern "C" void kernel_launch(void* const* d_in, const int* in_sizes, int n_in,
                              void* d_out, int out_size)
{
    const float* x  = (const float*)d_in[0];
    const float* wq = (const float*)d_in[1];
    const float* bq = (const float*)d_in[2];
    const float* wk = (const float*)d_in[3];
    const float* bk = (const float*)d_in[4];
    const float* wv = (const float*)d_in[5];
    const float* bv = (const float*)d_in[6];
    float* out = (float*)d_out;

    prep_w<<<768, 256>>>(wq, wk, wv);

    int n_bh = in_sizes[0] / 16384;   // B*H = 2048
    cudaFuncSetAttribute(attn_mma_kernel,
                         cudaFuncAttributeMaxDynamicSharedMemorySize, SMEM_B);
    attn_mma_kernel<<<n_bh / 2, 256, SMEM_B>>>(x, bq, bk, bv, out);
}

// round 12
// speedup vs baseline: 2.4452x; 1.1971x over previous
#include <cuda_runtime.h>
#include <cuda_bf16.h>
#include <cstdint>

typedef uint32_t u32;

// Pre-split transposed weights: Wt[n][k] bf16 hi/lo, row-major [256][256] (512B rows).
__device__ __align__(16) unsigned char g_Wh[3][131072];
__device__ __align__(16) unsigned char g_Wl[3][131072];

// ---- smem byte map ----
#define XHI_B   0            // X hi [128][132 words]
#define WB_B    67584        // 2 W half-buffers, each: hi[32][132w] + lo[32][132w]
#define WBUF_SZ 33792
#define QHI_B   135168       // Q hi [128][36w]   (phase B: Vt hi [64][68w] at VHI_B)
#define QLO_B   153600       // Q lo
#define VHI_B   135168
#define VLO_B   152576
#define SMEM_B  172032

#define MMA(d, a0, a1, a2, a3, b0, b1) \
    asm volatile("mma.sync.aligned.m16n8k16.row.col.f32.bf16.bf16.f32 " \
        "{%0,%1,%2,%3},{%4,%5,%6,%7},{%8,%9},{%0,%1,%2,%3};" \
        : "+f"((d)[0]), "+f"((d)[1]), "+f"((d)[2]), "+f"((d)[3]) \
        : "r"(a0), "r"(a1), "r"(a2), "r"(a3), "r"(b0), "r"(b1))

#define CPA16(dst, src) \
    asm volatile("cp.async.cg.shared.global [%0], [%1], 16;" :: "r"(dst), "l"(src))
#define CPC()  asm volatile("cp.async.commit_group;")
#define CPW1() asm volatile("cp.async.wait_group 1;")

__device__ __forceinline__ void split2(float f0, float f1, u32& hp, u32& lp) {
    asm("cvt.rn.bf16x2.f32 %0, %1, %2;" : "=r"(hp) : "f"(f1), "f"(f0));
    float h0 = __uint_as_float(hp << 16);
    float h1 = __uint_as_float(hp & 0xffff0000u);
    asm("cvt.rn.bf16x2.f32 %0, %1, %2;" : "=r"(lp) : "f"(f1 - h1), "f"(f0 - h0));
}

// ---------------- prep: transpose + split weights ----------------
__global__ void prep_w(const float* __restrict__ wq, const float* __restrict__ wk,
                       const float* __restrict__ wv)
{
    int idx = blockIdx.x * blockDim.x + threadIdx.x;
    if (idx >= 3 * 65536) return;
    int w = idx >> 16, e = idx & 65535;
    int k = e >> 8, n = e & 255;
    const float* W = (w == 0) ? wq : (w == 1) ? wk : wv;
    float f = W[k * 256 + n];
    __nv_bfloat16 h = __float2bfloat16(f);
    __nv_bfloat16 l = __float2bfloat16(f - __bfloat162float(h));
    *(__nv_bfloat16*)(g_Wh[w] + n * 512 + k * 2) = h;   // Wt[n][k]
    *(__nv_bfloat16*)(g_Wl[w] + n * 512 + k * 2) = l;
}

// prefetch one half-chunk (32 n rows, hi+lo) into a W buffer; commits one group.
// half index: 0..15 phase A (cc = i>>2, proj = (i>>1)&1 -> Q/K, h = i&1)
//             16..23 phase B (V: cc = (i-16)>>1, h = (i-16)&1)
__device__ __forceinline__ void pf_half(int idx, u32 dst, int tid) {
    int wsel, row0;
    if (idx < 16) { wsel = (idx >> 1) & 1; row0 = (idx >> 2) * 64 + (idx & 1) * 32; }
    else { int j = idx - 16; wsel = 2; row0 = (j >> 1) * 64 + (j & 1) * 32; }
    const unsigned char* gh = g_Wh[wsel] + row0 * 512;
    const unsigned char* gl = g_Wl[wsel] + row0 * 512;
#pragma unroll
    for (int i = 0; i < 4; i++) {
        int e = tid + i * 256;           // 0..1023: 32 rows x 32 x 16B
        int r = e >> 5, c = (e & 31) * 16;
        CPA16(dst + r * 528 + c, gh + r * 512 + c);
        CPA16(dst + 16896 + r * 528 + c, gl + r * 512 + c);
    }
    CPC();
}

// one half projection pass: 16 kk x 4 j-blocks x 3 split terms (Bhi@0, Blo@+4224w)
#define RUNHALF(ACC, JB) do {                                                   \
    CPW1(); __syncthreads();                                                    \
    const u32* wb = (const u32*)(smc + WB_B + cur * WBUF_SZ);                   \
    _Pragma("unroll")                                                           \
    for (int kk = 0; kk < 16; kk++) {                                           \
        int cw = kk * 8 + tq;                                                   \
        int i0 = (R + qd) * 132 + cw, i1 = i0 + 1056;                           \
        u32 ah0 = xh[i0], ah1 = xh[i1], ah2 = xh[i0 + 4], ah3 = xh[i1 + 4];     \
        _Pragma("unroll")                                                       \
        for (int j = 0; j < 4; j++) {                                           \
            int bi = (8 * j + qd) * 132 + cw;                                   \
            u32 b0 = wb[bi], b1 = wb[bi + 4];                                   \
            u32 c0 = wb[bi + 4224], c1 = wb[bi + 4228];                         \
            MMA(ACC[(JB) + j], ah0, ah1, ah2, ah3, b0, b1);                     \
            MMA(ACC[(JB) + j], alo[kk][0], alo[kk][1], alo[kk][2], alo[kk][3], b0, b1); \
            MMA(ACC[(JB) + j], ah0, ah1, ah2, ah3, c0, c1);                     \
        }                                                                       \
    }                                                                           \
    __syncthreads();                                                            \
    if (nextpf < 24) pf_half(nextpf, wbuf[cur], tid); else CPC();               \
    nextpf++; cur ^= 1;                                                         \
} while (0)

__global__ void __launch_bounds__(256, 1)
attn_mma_kernel(const float* __restrict__ x,
                const float* __restrict__ bq, const float* __restrict__ bk,
                const float* __restrict__ bv, float* __restrict__ out)
{
    extern __shared__ char smc[];
    u32 smb;
    asm("{ .reg .u64 t; cvta.to.shared.u64 t, %1; cvt.u32.u64 %0, t; }" : "=r"(smb) : "l"(smc));

    const int tid = threadIdx.x;
    const int w = tid >> 5, t = tid & 31;
    const int qd = t >> 2, tq = t & 3;
    const int R = w * 16;                 // warp's 16 stacked rows
    const int bh64 = (w >> 2) * 64;       // 0 (bh0) or 64 (bh1)

    const float* xg = x + (size_t)blockIdx.x * 32768;
    float*       og = out + (size_t)blockIdx.x * 32768;

    const u32* xh = (const u32*)(smc + XHI_B);
    u32* qh = (u32*)(smc + QHI_B);
    u32* ql = (u32*)(smc + QLO_B);

    // ---- stage X: hi -> XHI smem, lo -> WB region (temporary) ----
    {
        int row = tid >> 1, kh = (tid & 1) * 128;
        const float4* src = (const float4*)(xg + row * 256 + kh);
        u32* dh = (u32*)(smc + XHI_B);
        u32* dl = (u32*)(smc + WB_B);
        int base = row * 132 + (kh >> 1);
#pragma unroll 8
        for (int j2 = 0; j2 < 32; j2++) {
            float4 v = src[j2];
            u32 h0, l0, h1, l1;
            split2(v.x, v.y, h0, l0);
            split2(v.z, v.w, h1, l1);
            dh[base + 2 * j2] = h0; dh[base + 2 * j2 + 1] = h1;
            dl[base + 2 * j2] = l0; dl[base + 2 * j2 + 1] = l1;
        }
    }
    __syncthreads();

    // ---- A-lo fragments -> registers (64 regs), then WB region is free ----
    u32 alo[16][4];
    {
        const u32* xt = (const u32*)(smc + WB_B);
        int i0b = (R + qd) * 132 + tq;
#pragma unroll
        for (int kk = 0; kk < 16; kk++) {
            int i0 = i0b + kk * 8;
            alo[kk][0] = xt[i0];     alo[kk][1] = xt[i0 + 1056];
            alo[kk][2] = xt[i0 + 4]; alo[kk][3] = xt[i0 + 1060];
        }
    }
    __syncthreads();

    // ---- prime the W pipeline ----
    u32 wbuf[2] = { smb + WB_B, smb + WB_B + WBUF_SZ };
    pf_half(0, wbuf[0], tid);
    pf_half(1, wbuf[1], tid);
    int nextpf = 2, cur = 0;

    float S[8][4];
#pragma unroll
    for (int j = 0; j < 8; j++) { S[j][0] = S[j][1] = S[j][2] = S[j][3] = 0.f; }

    // ================= phase A: Q,K proj + S accumulation =================
    for (int cc = 0; cc < 4; cc++) {
        float acc[8][4];
        u32 khi[16], klo[16];
        // ---- Q projection ----
#pragma unroll
        for (int j = 0; j < 8; j++) { acc[j][0] = acc[j][1] = acc[j][2] = acc[j][3] = 0.f; }
        RUNHALF(acc, 0);
        RUNHALF(acc, 4);
        {   // Q epilogue: +bias, split, store to smem [v][36w]
            const float* bias = bq + cc * 64;
#pragma unroll
            for (int j = 0; j < 8; j++) {
                float2 bb = *(const float2*)(bias + 8 * j + tq * 2);
                int idx = (R + qd) * 36 + 4 * j + tq;
                u32 hp, lp;
                split2(acc[j][0] + bb.x, acc[j][1] + bb.y, hp, lp);
                qh[idx] = hp; ql[idx] = lp;
                split2(acc[j][2] + bb.x, acc[j][3] + bb.y, hp, lp);
                qh[idx + 288] = hp; ql[idx + 288] = lp;   // row+8
            }
        }
        // ---- K projection (stays in registers) ----
#pragma unroll
        for (int j = 0; j < 8; j++) { acc[j][0] = acc[j][1] = acc[j][2] = acc[j][3] = 0.f; }
        RUNHALF(acc, 0);
        RUNHALF(acc, 4);
        {
            const float* bias = bk + cc * 64;
#pragma unroll
            for (int j = 0; j < 8; j++) {
                float2 bb = *(const float2*)(bias + 8 * j + tq * 2);
                split2(acc[j][0] + bb.x, acc[j][1] + bb.y, khi[2 * j], klo[2 * j]);
                split2(acc[j][2] + bb.x, acc[j][3] + bb.y, khi[2 * j + 1], klo[2 * j + 1]);
            }
        }
        // ---- S += Kc * Qc^T  (A = K regs, B = Q smem; block-diagonal by bh) ----
#pragma unroll
        for (int kk = 0; kk < 4; kk++) {
#pragma unroll
            for (int j = 0; j < 8; j++) {
                int bi = (bh64 + 8 * j + qd) * 36 + kk * 8 + tq;
                u32 b0 = qh[bi], b1 = qh[bi + 4];
                u32 c0 = ql[bi], c1 = ql[bi + 4];
                MMA(S[j], khi[4 * kk], khi[4 * kk + 1], khi[4 * kk + 2], khi[4 * kk + 3], b0, b1);
                MMA(S[j], khi[4 * kk], khi[4 * kk + 1], khi[4 * kk + 2], khi[4 * kk + 3], c0, c1);
                MMA(S[j], klo[4 * kk], klo[4 * kk + 1], klo[4 * kk + 2], klo[4 * kk + 3], b0, b1);
            }
        }
    }

    // ================= softmax on S fragments (registers) =================
    u32 phi[16], plo[16];
    {
        float m0 = -1e30f, m1 = -1e30f;
#pragma unroll
        for (int j = 0; j < 8; j++) {
            m0 = fmaxf(m0, fmaxf(S[j][0], S[j][1]));
            m1 = fmaxf(m1, fmaxf(S[j][2], S[j][3]));
        }
        m0 = fmaxf(m0, __shfl_xor_sync(0xffffffffu, m0, 1));
        m0 = fmaxf(m0, __shfl_xor_sync(0xffffffffu, m0, 2));
        m1 = fmaxf(m1, __shfl_xor_sync(0xffffffffu, m1, 1));
        m1 = fmaxf(m1, __shfl_xor_sync(0xffffffffu, m1, 2));
        float s0 = 0.f, s1 = 0.f;
#pragma unroll
        for (int j = 0; j < 8; j++) {
            S[j][0] = __expf(S[j][0] - m0); S[j][1] = __expf(S[j][1] - m0);
            S[j][2] = __expf(S[j][2] - m1); S[j][3] = __expf(S[j][3] - m1);
            s0 += S[j][0] + S[j][1];
            s1 += S[j][2] + S[j][3];
        }
        s0 += __shfl_xor_sync(0xffffffffu, s0, 1);
        s0 += __shfl_xor_sync(0xffffffffu, s0, 2);
        s1 += __shfl_xor_sync(0xffffffffu, s1, 1);
        s1 += __shfl_xor_sync(0xffffffffu, s1, 2);
        float i0 = 1.f / s0, i1 = 1.f / s1;
#pragma unroll
        for (int j = 0; j < 8; j++) {
            split2(S[j][0] * i0, S[j][1] * i0, phi[2 * j], plo[2 * j]);
            split2(S[j][2] * i1, S[j][3] * i1, phi[2 * j + 1], plo[2 * j + 1]);
        }
    }

    // ================= phase B: V proj + O = P V + gate =================
    const u32* vhw = (const u32*)(smc + VHI_B);
    const u32* vlw = (const u32*)(smc + VLO_B);
    for (int cc = 0; cc < 4; cc++) {
        float acc[8][4];
#pragma unroll
        for (int j = 0; j < 8; j++) { acc[j][0] = acc[j][1] = acc[j][2] = acc[j][3] = 0.f; }
        RUNHALF(acc, 0);
        RUNHALF(acc, 4);
        {   // V epilogue: +bias, split, transposed store Vt[c][v]
            __nv_bfloat16* vth = (__nv_bfloat16*)(smc + VHI_B);
            __nv_bfloat16* vtl = (__nv_bfloat16*)(smc + VLO_B);
            const float* bias = bv + cc * 64;
            int v0 = R + qd;
#pragma unroll
            for (int j = 0; j < 8; j++) {
                float2 bb = *(const float2*)(bias + 8 * j + tq * 2);
                int c0 = 8 * j + tq * 2;
                float f0 = acc[j][0] + bb.x, f1 = acc[j][1] + bb.y;
                float f2 = acc[j][2] + bb.x, f3 = acc[j][3] + bb.y;
                __nv_bfloat16 h;
                h = __float2bfloat16(f0); vth[c0 * 136 + v0] = h;
                vtl[c0 * 136 + v0] = __float2bfloat16(f0 - __bfloat162float(h));
                h = __float2bfloat16(f1); vth[(c0 + 1) * 136 + v0] = h;
                vtl[(c0 + 1) * 136 + v0] = __float2bfloat16(f1 - __bfloat162float(h));
                h = __float2bfloat16(f2); vth[c0 * 136 + v0 + 8] = h;
                vtl[c0 * 136 + v0 + 8] = __float2bfloat16(f2 - __bfloat162float(h));
                h = __float2bfloat16(f3); vth[(c0 + 1) * 136 + v0 + 8] = h;
                vtl[(c0 + 1) * 136 + v0 + 8] = __float2bfloat16(f3 - __bfloat162float(h));
            }
        }
        __syncthreads();
        // ---- O = P * Vc (A = P regs, B = Vt smem) ----
        float O[8][4];
#pragma unroll
        for (int j = 0; j < 8; j++) { O[j][0] = O[j][1] = O[j][2] = O[j][3] = 0.f; }
#pragma unroll
        for (int kkv = 0; kkv < 4; kkv++) {
#pragma unroll
            for (int j = 0; j < 8; j++) {
                int bi = (8 * j + qd) * 68 + (bh64 >> 1) + kkv * 8 + tq;
                u32 b0 = vhw[bi], b1 = vhw[bi + 4];
                u32 c0 = vlw[bi], c1 = vlw[bi + 4];
                MMA(O[j], phi[4 * kkv], phi[4 * kkv + 1], phi[4 * kkv + 2], phi[4 * kkv + 3], b0, b1);
                MMA(O[j], phi[4 * kkv], phi[4 * kkv + 1], phi[4 * kkv + 2], phi[4 * kkv + 3], c0, c1);
                MMA(O[j], plo[4 * kkv], plo[4 * kkv + 1], plo[4 * kkv + 2], plo[4 * kkv + 3], b0, b1);
            }
        }
        // ---- gate with x, store ----
        {
            int r0 = R + qd;
#pragma unroll
            for (int j = 0; j < 8; j++) {
                int col = cc * 64 + 8 * j + tq * 2;
                float2 x0 = *(const float2*)(xg + r0 * 256 + col);
                float2 x1 = *(const float2*)(xg + (r0 + 8) * 256 + col);
                float2 o0 = make_float2(O[j][0] * x0.x, O[j][1] * x0.y);
                float2 o1 = make_float2(O[j][2] * x1.x, O[j][3] * x1.y);
                *(float2*)(og + r0 * 256 + col) = o0;
                *(float2*)(og + (r0 + 8) * 256 + col) = o1;
            }
        }
    }
}

extern "C" void kernel_launch(void* const* d_in, const int* in_sizes, int n_in,
                              void* d_out, int out_size)
{
    const float* x  = (const float*)d_in[0];
    const float* wq = (const float*)d_in[1];
    const float* bq = (const float*)d_in[2];
    const float* wk = (const float*)d_in[3];
    const float* bk = (const float*)d_in[4];
    const float* wv = (const float*)d_in[5];
    const float* bv = (const float*)d_in[6];
    float* out = (float*)d_out;

    prep_w<<<768, 256>>>(wq, wk, wv);

    int n_bh = in_sizes[0] / 16384;   // B*H = 2048
    cudaFuncSetAttribute(attn_mma_kernel,
                         cudaFuncAttributeMaxDynamicSharedMemorySize, SMEM_B);
    attn_mma_kernel<<<n_bh / 2, 256, SMEM_B>>>(x, bq, bk, bv, out);
}

// round 13
// speedup vs baseline: 2.4520x; 1.0028x over previous
#include <cuda_runtime.h>
#include <cuda_bf16.h>
#include <cstdint>

typedef uint32_t u32;

// Pre-split transposed weights: Wt[n][k] bf16 hi/lo, row-major [256][256] (512B rows).
__device__ __align__(16) unsigned char g_Wh[3][131072];
__device__ __align__(16) unsigned char g_Wl[3][131072];

// ---- smem byte map ----
#define XHI_B   0            // X hi [128][132 words] (528B rows)
#define WB_B    67584        // 2 W half-buffers, each: hi[32][132w] + lo[32][132w]
#define WBUF_SZ 33792
#define QHI_B   135168       // Q hi [128][36w] (144B rows)   (phase B: Vt hi [64][68w])
#define QLO_B   153600       // Q lo (+18432)
#define VHI_B   135168       // Vt hi (272B rows)
#define VLO_B   152576       // Vt lo (+17408)
#define SMEM_B  172032

#define MMA(d, a0, a1, a2, a3, b0, b1) \
    asm volatile("mma.sync.aligned.m16n8k16.row.col.f32.bf16.bf16.f32 " \
        "{%0,%1,%2,%3},{%4,%5,%6,%7},{%8,%9},{%0,%1,%2,%3};" \
        : "+f"((d)[0]), "+f"((d)[1]), "+f"((d)[2]), "+f"((d)[3]) \
        : "r"(a0), "r"(a1), "r"(a2), "r"(a3), "r"(b0), "r"(b1))

#define LDSM4(r0, r1, r2, r3, a) \
    asm volatile("ldmatrix.sync.aligned.m8n8.x4.shared.b16 {%0,%1,%2,%3}, [%4];" \
        : "=r"(r0), "=r"(r1), "=r"(r2), "=r"(r3) : "r"(a))

#define CPA16(dst, src) \
    asm volatile("cp.async.cg.shared.global [%0], [%1], 16;" :: "r"(dst), "l"(src))
#define CPC()  asm volatile("cp.async.commit_group;")
#define CPW1() asm volatile("cp.async.wait_group 1;")

__device__ __forceinline__ void split2(float f0, float f1, u32& hp, u32& lp) {
    asm("cvt.rn.bf16x2.f32 %0, %1, %2;" : "=r"(hp) : "f"(f1), "f"(f0));
    float h0 = __uint_as_float(hp << 16);
    float h1 = __uint_as_float(hp & 0xffff0000u);
    asm("cvt.rn.bf16x2.f32 %0, %1, %2;" : "=r"(lp) : "f"(f1 - h1), "f"(f0 - h0));
}

// ---------------- prep: transpose + split weights ----------------
__global__ void prep_w(const float* __restrict__ wq, const float* __restrict__ wk,
                       const float* __restrict__ wv)
{
    int idx = blockIdx.x * blockDim.x + threadIdx.x;
    if (idx >= 3 * 65536) return;
    int w = idx >> 16, e = idx & 65535;
    int k = e >> 8, n = e & 255;
    const float* W = (w == 0) ? wq : (w == 1) ? wk : wv;
    float f = W[k * 256 + n];
    __nv_bfloat16 h = __float2bfloat16(f);
    __nv_bfloat16 l = __float2bfloat16(f - __bfloat162float(h));
    *(__nv_bfloat16*)(g_Wh[w] + n * 512 + k * 2) = h;   // Wt[n][k]
    *(__nv_bfloat16*)(g_Wl[w] + n * 512 + k * 2) = l;
}

// prefetch one half-chunk (32 n rows, hi+lo) into a W buffer; commits one group.
__device__ __forceinline__ void pf_half(int idx, u32 dst, int tid) {
    int wsel, row0;
    if (idx < 16) { wsel = (idx >> 1) & 1; row0 = (idx >> 2) * 64 + (idx & 1) * 32; }
    else { int j = idx - 16; wsel = 2; row0 = (j >> 1) * 64 + (j & 1) * 32; }
    const unsigned char* gh = g_Wh[wsel] + row0 * 512;
    const unsigned char* gl = g_Wl[wsel] + row0 * 512;
#pragma unroll
    for (int i = 0; i < 4; i++) {
        int e = tid + i * 256;           // 0..1023: 32 rows x 32 x 16B
        int r = e >> 5, c = (e & 31) * 16;
        CPA16(dst + r * 528 + c, gh + r * 512 + c);
        CPA16(dst + 16896 + r * 528 + c, gl + r * 512 + c);
    }
    CPC();
}

// one half projection pass: 16 kk x (1 A-ldsm + 4 j x (1 B-ldsm + 3 MMA))
#define RUNHALF(ACC, JB) do {                                                   \
    CPW1(); __syncthreads();                                                    \
    u32 wbase = wAddrT + (u32)cur * WBUF_SZ;                                    \
    _Pragma("unroll")                                                           \
    for (int kk = 0; kk < 16; kk++) {                                           \
        u32 ah0, ah1, ah2, ah3;                                                 \
        LDSM4(ah0, ah1, ah2, ah3, aAddrT + kk * 32);                            \
        _Pragma("unroll")                                                       \
        for (int j = 0; j < 4; j++) {                                           \
            u32 b0, b1, c0, c1;                                                 \
            LDSM4(b0, b1, c0, c1, wbase + j * 4224 + kk * 32);                  \
            MMA(ACC[(JB) + j], ah0, ah1, ah2, ah3, b0, b1);                     \
            MMA(ACC[(JB) + j], alo[kk][0], alo[kk][1], alo[kk][2], alo[kk][3], b0, b1); \
            MMA(ACC[(JB) + j], ah0, ah1, ah2, ah3, c0, c1);                     \
        }                                                                       \
    }                                                                           \
    __syncthreads();                                                            \
    if (nextpf < 24) pf_half(nextpf, wbuf[cur], tid); else CPC();               \
    nextpf++; cur ^= 1;                                                         \
} while (0)

__global__ void __launch_bounds__(256, 1)
attn_mma_kernel(const float* __restrict__ x,
                const float* __restrict__ bq, const float* __restrict__ bk,
                const float* __restrict__ bv, float* __restrict__ out)
{
    extern __shared__ char smc[];
    u32 smb;
    asm("{ .reg .u64 t; cvta.to.shared.u64 t, %1; cvt.u32.u64 %0, t; }" : "=r"(smb) : "l"(smc));

    const int tid = threadIdx.x;
    const int w = tid >> 5, t = tid & 31;
    const int qd = t >> 2, tq = t & 3;
    const int R = w * 16;                 // warp's 16 stacked rows
    const int bh64 = (w >> 2) * 64;       // 0 (bh0) or 64 (bh1)

    // ldmatrix thread-role decomposition
    const int tm8 = t & 7;                // row within 8-row matrix
    const int g8  = (t >> 3) & 1;         // k-half select (matrices 1,3)
    const int g16 = t >> 4;               // hi/lo buffer select (matrices 2,3)

    const float* xg = x + (size_t)blockIdx.x * 32768;
    float*       og = out + (size_t)blockIdx.x * 32768;

    u32* qh = (u32*)(smc + QHI_B);
    u32* ql = (u32*)(smc + QLO_B);

    // ---- stage X: hi -> XHI smem, lo -> WB region (temporary) ----
    {
        int row = tid >> 1, kh = (tid & 1) * 128;
        const float4* src = (const float4*)(xg + row * 256 + kh);
        u32* dh = (u32*)(smc + XHI_B);
        u32* dl = (u32*)(smc + WB_B);
        int base = row * 132 + (kh >> 1);
#pragma unroll 8
        for (int j2 = 0; j2 < 32; j2++) {
            float4 v = src[j2];
            u32 h0, l0, h1, l1;
            split2(v.x, v.y, h0, l0);
            split2(v.z, v.w, h1, l1);
            dh[base + 2 * j2] = h0; dh[base + 2 * j2 + 1] = h1;
            dl[base + 2 * j2] = l0; dl[base + 2 * j2 + 1] = l1;
        }
    }
    __syncthreads();

    // ---- A-lo fragments -> registers (64 regs), then WB region is free ----
    u32 alo[16][4];
    {
        const u32* xt = (const u32*)(smc + WB_B);
        int i0b = (R + qd) * 132 + tq;
#pragma unroll
        for (int kk = 0; kk < 16; kk++) {
            int i0 = i0b + kk * 8;
            alo[kk][0] = xt[i0];     alo[kk][1] = xt[i0 + 1056];
            alo[kk][2] = xt[i0 + 4]; alo[kk][3] = xt[i0 + 1060];
        }
    }
    __syncthreads();

    // ---- per-thread ldmatrix base addresses ----
    const u32 aAddrT = smb + XHI_B + (u32)(R + tm8 + 8 * g8) * 528 + (u32)g16 * 16;
    const u32 wAddrT = smb + WB_B + (u32)tm8 * 528 + (u32)g8 * 16 + (u32)g16 * 16896;
    const u32 qAddrT = smb + QHI_B + (u32)(bh64 + tm8) * 144 + (u32)g8 * 16 + (u32)g16 * 18432;
    const u32 vAddrT = smb + VHI_B + (u32)tm8 * 272 + (u32)bh64 * 2 + (u32)g8 * 16 + (u32)g16 * 17408;

    // ---- prime the W pipeline ----
    u32 wbuf[2] = { smb + WB_B, smb + WB_B + WBUF_SZ };
    pf_half(0, wbuf[0], tid);
    pf_half(1, wbuf[1], tid);
    int nextpf = 2, cur = 0;

    float S[8][4];
#pragma unroll
    for (int j = 0; j < 8; j++) { S[j][0] = S[j][1] = S[j][2] = S[j][3] = 0.f; }

    // ================= phase A: Q,K proj + S accumulation =================
    for (int cc = 0; cc < 4; cc++) {
        float acc[8][4];
        u32 khi[16], klo[16];
        // ---- Q projection ----
#pragma unroll
        for (int j = 0; j < 8; j++) { acc[j][0] = acc[j][1] = acc[j][2] = acc[j][3] = 0.f; }
        RUNHALF(acc, 0);
        RUNHALF(acc, 4);
        {   // Q epilogue: +bias, split, store to smem [v][36w]
            const float* bias = bq + cc * 64;
#pragma unroll
            for (int j = 0; j < 8; j++) {
                float2 bb = *(const float2*)(bias + 8 * j + tq * 2);
                int idx = (R + qd) * 36 + 4 * j + tq;
                u32 hp, lp;
                split2(acc[j][0] + bb.x, acc[j][1] + bb.y, hp, lp);
                qh[idx] = hp; ql[idx] = lp;
                split2(acc[j][2] + bb.x, acc[j][3] + bb.y, hp, lp);
                qh[idx + 288] = hp; ql[idx + 288] = lp;   // row+8
            }
        }
        // ---- K projection (stays in registers) ----
#pragma unroll
        for (int j = 0; j < 8; j++) { acc[j][0] = acc[j][1] = acc[j][2] = acc[j][3] = 0.f; }
        RUNHALF(acc, 0);
        RUNHALF(acc, 4);
        {
            const float* bias = bk + cc * 64;
#pragma unroll
            for (int j = 0; j < 8; j++) {
                float2 bb = *(const float2*)(bias + 8 * j + tq * 2);
                split2(acc[j][0] + bb.x, acc[j][1] + bb.y, khi[2 * j], klo[2 * j]);
                split2(acc[j][2] + bb.x, acc[j][3] + bb.y, khi[2 * j + 1], klo[2 * j + 1]);
            }
        }
        // ---- S += Kc * Qc^T  (A = K regs, B = Q smem via ldmatrix) ----
#pragma unroll
        for (int kk = 0; kk < 4; kk++) {
#pragma unroll
            for (int j = 0; j < 8; j++) {
                u32 b0, b1, c0, c1;
                LDSM4(b0, b1, c0, c1, qAddrT + (u32)j * 1152 + (u32)kk * 32);
                MMA(S[j], khi[4 * kk], khi[4 * kk + 1], khi[4 * kk + 2], khi[4 * kk + 3], b0, b1);
                MMA(S[j], khi[4 * kk], khi[4 * kk + 1], khi[4 * kk + 2], khi[4 * kk + 3], c0, c1);
                MMA(S[j], klo[4 * kk], klo[4 * kk + 1], klo[4 * kk + 2], klo[4 * kk + 3], b0, b1);
            }
        }
    }

    // ================= softmax on S fragments (registers) =================
    u32 phi[16], plo[16];
    {
        float m0 = -1e30f, m1 = -1e30f;
#pragma unroll
        for (int j = 0; j < 8; j++) {
            m0 = fmaxf(m0, fmaxf(S[j][0], S[j][1]));
            m1 = fmaxf(m1, fmaxf(S[j][2], S[j][3]));
        }
        m0 = fmaxf(m0, __shfl_xor_sync(0xffffffffu, m0, 1));
        m0 = fmaxf(m0, __shfl_xor_sync(0xffffffffu, m0, 2));
        m1 = fmaxf(m1, __shfl_xor_sync(0xffffffffu, m1, 1));
        m1 = fmaxf(m1, __shfl_xor_sync(0xffffffffu, m1, 2));
        float s0 = 0.f, s1 = 0.f;
#pragma unroll
        for (int j = 0; j < 8; j++) {
            S[j][0] = __expf(S[j][0] - m0); S[j][1] = __expf(S[j][1] - m0);
            S[j][2] = __expf(S[j][2] - m1); S[j][3] = __expf(S[j][3] - m1);
            s0 += S[j][0] + S[j][1];
            s1 += S[j][2] + S[j][3];
        }
        s0 += __shfl_xor_sync(0xffffffffu, s0, 1);
        s0 += __shfl_xor_sync(0xffffffffu, s0, 2);
        s1 += __shfl_xor_sync(0xffffffffu, s1, 1);
        s1 += __shfl_xor_sync(0xffffffffu, s1, 2);
        float i0 = 1.f / s0, i1 = 1.f / s1;
#pragma unroll
        for (int j = 0; j < 8; j++) {
            split2(S[j][0] * i0, S[j][1] * i0, phi[2 * j], plo[2 * j]);
            split2(S[j][2] * i1, S[j][3] * i1, phi[2 * j + 1], plo[2 * j + 1]);
        }
    }

    // ================= phase B: V proj + O = P V + gate =================
    for (int cc = 0; cc < 4; cc++) {
        float acc[8][4];
#pragma unroll
        for (int j = 0; j < 8; j++) { acc[j][0] = acc[j][1] = acc[j][2] = acc[j][3] = 0.f; }
        RUNHALF(acc, 0);
        RUNHALF(acc, 4);
        {   // V epilogue: +bias, split, transposed store Vt[c][v]
            __nv_bfloat16* vth = (__nv_bfloat16*)(smc + VHI_B);
            __nv_bfloat16* vtl = (__nv_bfloat16*)(smc + VLO_B);
            const float* bias = bv + cc * 64;
            int v0 = R + qd;
#pragma unroll
            for (int j = 0; j < 8; j++) {
                float2 bb = *(const float2*)(bias + 8 * j + tq * 2);
                int c0 = 8 * j + tq * 2;
                float f0 = acc[j][0] + bb.x, f1 = acc[j][1] + bb.y;
                float f2 = acc[j][2] + bb.x, f3 = acc[j][3] + bb.y;
                __nv_bfloat16 h;
                h = __float2bfloat16(f0); vth[c0 * 136 + v0] = h;
                vtl[c0 * 136 + v0] = __float2bfloat16(f0 - __bfloat162float(h));
                h = __float2bfloat16(f1); vth[(c0 + 1) * 136 + v0] = h;
                vtl[(c0 + 1) * 136 + v0] = __float2bfloat16(f1 - __bfloat162float(h));
                h = __float2bfloat16(f2); vth[c0 * 136 + v0 + 8] = h;
                vtl[c0 * 136 + v0 + 8] = __float2bfloat16(f2 - __bfloat162float(h));
                h = __float2bfloat16(f3); vth[(c0 + 1) * 136 + v0 + 8] = h;
                vtl[(c0 + 1) * 136 + v0 + 8] = __float2bfloat16(f3 - __bfloat162float(h));
            }
        }
        __syncthreads();
        // ---- O = P * Vc (A = P regs, B = Vt smem via ldmatrix) ----
        float O[8][4];
#pragma unroll
        for (int j = 0; j < 8; j++) { O[j][0] = O[j][1] = O[j][2] = O[j][3] = 0.f; }
#pragma unroll
        for (int kkv = 0; kkv < 4; kkv++) {
#pragma unroll
            for (int j = 0; j < 8; j++) {
                u32 b0, b1, c0, c1;
                LDSM4(b0, b1, c0, c1, vAddrT + (u32)j * 2176 + (u32)kkv * 32);
                MMA(O[j], phi[4 * kkv], phi[4 * kkv + 1], phi[4 * kkv + 2], phi[4 * kkv + 3], b0, b1);
                MMA(O[j], phi[4 * kkv], phi[4 * kkv + 1], phi[4 * kkv + 2], phi[4 * kkv + 3], c0, c1);
                MMA(O[j], plo[4 * kkv], plo[4 * kkv + 1], plo[4 * kkv + 2], plo[4 * kkv + 3], b0, b1);
            }
        }
        // ---- gate with x, store ----
        {
            int r0 = R + qd;
#pragma unroll
            for (int j = 0; j < 8; j++) {
                int col = cc * 64 + 8 * j + tq * 2;
                float2 x0 = *(const float2*)(xg + r0 * 256 + col);
                float2 x1 = *(const float2*)(xg + (r0 + 8) * 256 + col);
                float2 o0 = make_float2(O[j][0] * x0.x, O[j][1] * x0.y);
                float2 o1 = make_float2(O[j][2] * x1.x, O[j][3] * x1.y);
                *(float2*)(og + r0 * 256 + col) = o0;
                *(float2*)(og + (r0 + 8) * 256 + col) = o1;
            }
        }
        if (cc < 3) __syncthreads();   // Vt buffer reused next cc
    }
}

extern "C" void kernel_launch(void* const* d_in, const int* in_sizes, int n_in,
                              void* d_out, int out_size)
{
    const float* x  = (const float*)d_in[0];
    const float* wq = (const float*)d_in[1];
    const float* bq = (const float*)d_in[2];
    const float* wk = (const float*)d_in[3];
    const float* bk = (const float*)d_in[4];
    const float* wv = (const float*)d_in[5];
    const float* bv = (const float*)d_in[6];
    float* out = (float*)d_out;

    prep_w<<<768, 256>>>(wq, wk, wv);

    int n_bh = in_sizes[0] / 16384;   // B*H = 2048
    cudaFuncSetAttribute(attn_mma_kernel,
                         cudaFuncAttributeMaxDynamicSharedMemorySize, SMEM_B);
    attn_mma_kernel<<<n_bh / 2, 256, SMEM_B>>>(x, bq, bk, bv, out);
}

// round 14
// speedup vs baseline: 2.4677x; 1.0064x over previous
#include <cuda_runtime.h>
#include <cuda_bf16.h>
#include <cstdint>

typedef uint32_t u32;

// Pre-split transposed weights: Wt[n][k] bf16 hi/lo, row-major [256][256] (512B rows).
__device__ __align__(16) unsigned char g_Wh[3][131072];
__device__ __align__(16) unsigned char g_Wl[3][131072];

// ---- smem byte map (all regions XOR-swizzled: 16B-unit col ^= (row & 7)) ----
#define XH_B   0             // X hi [128 rows][512B]
#define XL_B   65536         // X lo
#define WB_B   131072        // 2 W buffers, each: hi[32][512B] + lo[32][512B]
#define WBUF_SZ 32768
#define QH_B   196608        // Q hi [128 rows][128B]   (phase B: Vt hi [64 rows][256B])
#define QL_B   212992        // Q lo                    (phase B: Vt lo)
#define SMEM_B 229376

#define MMA(d, a0, a1, a2, a3, b0, b1) \
    asm volatile("mma.sync.aligned.m16n8k16.row.col.f32.bf16.bf16.f32 " \
        "{%0,%1,%2,%3},{%4,%5,%6,%7},{%8,%9},{%0,%1,%2,%3};" \
        : "+f"((d)[0]), "+f"((d)[1]), "+f"((d)[2]), "+f"((d)[3]) \
        : "r"(a0), "r"(a1), "r"(a2), "r"(a3), "r"(b0), "r"(b1))

#define LDSM4(r0, r1, r2, r3, a) \
    asm volatile("ldmatrix.sync.aligned.m8n8.x4.shared.b16 {%0,%1,%2,%3}, [%4];" \
        : "=r"(r0), "=r"(r1), "=r"(r2), "=r"(r3) : "r"(a))

#define CPA16(dst, src) \
    asm volatile("cp.async.cg.shared.global [%0], [%1], 16;" :: "r"(dst), "l"(src))
#define CPC()  asm volatile("cp.async.commit_group;")
#define CPW1() asm volatile("cp.async.wait_group 1;")

__device__ __forceinline__ void split2(float f0, float f1, u32& hp, u32& lp) {
    asm("cvt.rn.bf16x2.f32 %0, %1, %2;" : "=r"(hp) : "f"(f1), "f"(f0));
    float h0 = __uint_as_float(hp << 16);
    float h1 = __uint_as_float(hp & 0xffff0000u);
    asm("cvt.rn.bf16x2.f32 %0, %1, %2;" : "=r"(lp) : "f"(f1 - h1), "f"(f0 - h0));
}

// ---------------- prep: transpose + split weights ----------------
__global__ void prep_w(const float* __restrict__ wq, const float* __restrict__ wk,
                       const float* __restrict__ wv)
{
    int idx = blockIdx.x * blockDim.x + threadIdx.x;
    if (idx >= 3 * 65536) return;
    int w = idx >> 16, e = idx & 65535;
    int k = e >> 8, n = e & 255;
    const float* W = (w == 0) ? wq : (w == 1) ? wk : wv;
    float f = W[k * 256 + n];
    __nv_bfloat16 h = __float2bfloat16(f);
    __nv_bfloat16 l = __float2bfloat16(f - __bfloat162float(h));
    *(__nv_bfloat16*)(g_Wh[w] + n * 512 + k * 2) = h;   // Wt[n][k]
    *(__nv_bfloat16*)(g_Wl[w] + n * 512 + k * 2) = l;
}

// prefetch one half-chunk (32 n rows, hi+lo) into a W buffer, swizzled.
__device__ __forceinline__ void pf_half(int idx, u32 dst, int tid) {
    int wsel, row0;
    if (idx < 16) { wsel = (idx >> 1) & 1; row0 = (idx >> 2) * 64 + (idx & 1) * 32; }
    else { int j = idx - 16; wsel = 2; row0 = (j >> 1) * 64 + (j & 1) * 32; }
    const unsigned char* gh = g_Wh[wsel] + row0 * 512;
    const unsigned char* gl = g_Wl[wsel] + row0 * 512;
#pragma unroll
    for (int i = 0; i < 4; i++) {
        int e = tid + i * 256;               // 0..1023: 32 rows x 32 units
        int r = e >> 5, c = e & 31;
        u32 so = (u32)(r * 512 + ((c ^ (r & 7)) << 4));
        CPA16(dst + so, gh + r * 512 + c * 16);
        CPA16(dst + 16384 + so, gl + r * 512 + c * 16);
    }
    CPC();
}

// one half projection pass: 16 kk x (2 A-ldsm + 4 j x (1 B-ldsm + 3 MMA))
#define RUNHALF(ACC, JB) do {                                                   \
    CPW1(); __syncthreads();                                                    \
    u32 wbase = wAddrT + (u32)cur * WBUF_SZ;                                    \
    _Pragma("unroll")                                                           \
    for (int kk = 0; kk < 16; kk++) {                                           \
        u32 koff = (u32)(((kk * 2) ^ txe) << 4);                                \
        u32 ah0, ah1, ah2, ah3, al0, al1, al2, al3;                             \
        LDSM4(ah0, ah1, ah2, ah3, aXH + koff);                                  \
        LDSM4(al0, al1, al2, al3, aXL + koff);                                  \
        _Pragma("unroll")                                                       \
        for (int j = 0; j < 4; j++) {                                           \
            u32 b0, b1, c0, c1;                                                 \
            LDSM4(b0, b1, c0, c1, wbase + (u32)(j * 4096) + koff);              \
            MMA(ACC[(JB) + j], ah0, ah1, ah2, ah3, b0, b1);                     \
            MMA(ACC[(JB) + j], al0, al1, al2, al3, b0, b1);                     \
            MMA(ACC[(JB) + j], ah0, ah1, ah2, ah3, c0, c1);                     \
        }                                                                       \
    }                                                                           \
    __syncthreads();                                                            \
    if (nextpf < 24) pf_half(nextpf, wbuf[cur], tid); else CPC();               \
    nextpf++; cur ^= 1;                                                         \
} while (0)

__global__ void __launch_bounds__(256, 1)
attn_mma_kernel(const float* __restrict__ x,
                const float* __restrict__ bq, const float* __restrict__ bk,
                const float* __restrict__ bv, float* __restrict__ out)
{
    extern __shared__ char smc[];
    u32 smb;
    asm("{ .reg .u64 t; cvta.to.shared.u64 t, %1; cvt.u32.u64 %0, t; }" : "=r"(smb) : "l"(smc));

    const int tid = threadIdx.x;
    const int w = tid >> 5, t = tid & 31;
    const int qd = t >> 2, tq = t & 3;
    const int R = w * 16;                 // warp's 16 stacked rows
    const int bh64 = (w >> 2) * 64;       // 0 (bh0) or 64 (bh1)

    // ldmatrix thread-role decomposition
    const int tm8 = t & 7;
    const int g8  = (t >> 3) & 1;
    const int g16 = t >> 4;
    const int txe = tm8 & 6, txo = tm8 & 1;

    const float* xg = x + (size_t)blockIdx.x * 32768;
    float*       og = out + (size_t)blockIdx.x * 32768;

    u32* qh = (u32*)(smc + QH_B);
    u32* ql = (u32*)(smc + QL_B);

    // ---- stage X: hi -> XH, lo -> XL (swizzled) ----
    {
        int row = tid >> 1, kh = (tid & 1) * 128;
        const float4* src = (const float4*)(xg + row * 256 + kh);
        int rx = row & 7;
        char* dh = smc + XH_B + row * 512;
        char* dl = smc + XL_B + row * 512;
#pragma unroll 8
        for (int j2 = 0; j2 < 32; j2++) {
            float4 v = src[j2];
            int unit = (kh >> 3) + (j2 >> 1);
            u32 off = (u32)(((unit ^ rx) << 4) + ((j2 & 1) << 3));
            u32 h0, l0, h1, l1;
            split2(v.x, v.y, h0, l0);
            split2(v.z, v.w, h1, l1);
            *(u32*)(dh + off) = h0; *(u32*)(dh + off + 4) = h1;
            *(u32*)(dl + off) = l0; *(u32*)(dl + off + 4) = l1;
        }
    }

    // ---- per-thread ldmatrix base addresses (swizzled layouts) ----
    const u32 aXH = smb + XH_B + (u32)(R + tm8 + 8 * g8) * 512 + (u32)((g16 ^ txo) << 4);
    const u32 aXL = aXH + 65536;
    const u32 wAddrT = smb + WB_B + (u32)g16 * 16384 + (u32)tm8 * 512 + (u32)((g8 ^ txo) << 4);
    const u32 qAddrT = smb + QH_B + (u32)g16 * 16384 + (u32)(bh64 + tm8) * 128 + (u32)((g8 ^ txo) << 4);
    const u32 vAddrT = smb + QH_B + (u32)g16 * 16384 + (u32)tm8 * 256 + (u32)((bh64 >> 3) << 4) + (u32)((g8 ^ txo) << 4);

    // ---- prime the W pipeline ----
    u32 wbuf[2] = { smb + WB_B, smb + WB_B + WBUF_SZ };
    pf_half(0, wbuf[0], tid);
    pf_half(1, wbuf[1], tid);
    int nextpf = 2, cur = 0;

    float S[8][4];
#pragma unroll
    for (int j = 0; j < 8; j++) { S[j][0] = S[j][1] = S[j][2] = S[j][3] = 0.f; }

    // ================= phase A: Q,K proj + S accumulation =================
    for (int cc = 0; cc < 4; cc++) {
        float acc[8][4];
        u32 khi[16], klo[16];
        // ---- Q projection ----
#pragma unroll
        for (int j = 0; j < 8; j++) { acc[j][0] = acc[j][1] = acc[j][2] = acc[j][3] = 0.f; }
        RUNHALF(acc, 0);
        RUNHALF(acc, 4);
        {   // Q epilogue: +bias, split, swizzled store [row][128B]
            const float* bias = bq + cc * 64;
            int r0 = R + qd;
#pragma unroll
            for (int j = 0; j < 8; j++) {
                float2 bb = *(const float2*)(bias + 8 * j + tq * 2);
                int wo = ((j ^ qd) << 2) + tq;
                u32 hp, lp;
                split2(acc[j][0] + bb.x, acc[j][1] + bb.y, hp, lp);
                qh[r0 * 32 + wo] = hp; ql[r0 * 32 + wo] = lp;
                split2(acc[j][2] + bb.x, acc[j][3] + bb.y, hp, lp);
                qh[(r0 + 8) * 32 + wo] = hp; ql[(r0 + 8) * 32 + wo] = lp;
            }
        }
        // ---- K projection (stays in registers) ----
#pragma unroll
        for (int j = 0; j < 8; j++) { acc[j][0] = acc[j][1] = acc[j][2] = acc[j][3] = 0.f; }
        RUNHALF(acc, 0);
        RUNHALF(acc, 4);
        {
            const float* bias = bk + cc * 64;
#pragma unroll
            for (int j = 0; j < 8; j++) {
                float2 bb = *(const float2*)(bias + 8 * j + tq * 2);
                split2(acc[j][0] + bb.x, acc[j][1] + bb.y, khi[2 * j], klo[2 * j]);
                split2(acc[j][2] + bb.x, acc[j][3] + bb.y, khi[2 * j + 1], klo[2 * j + 1]);
            }
        }
        // ---- S += Kc * Qc^T  (A = K regs, B = Q smem via ldmatrix) ----
#pragma unroll
        for (int kk = 0; kk < 4; kk++) {
            u32 koff = (u32)(((kk * 2) ^ txe) << 4);
#pragma unroll
            for (int j = 0; j < 8; j++) {
                u32 b0, b1, c0, c1;
                LDSM4(b0, b1, c0, c1, qAddrT + (u32)(j * 1024) + koff);
                MMA(S[j], khi[4 * kk], khi[4 * kk + 1], khi[4 * kk + 2], khi[4 * kk + 3], b0, b1);
                MMA(S[j], khi[4 * kk], khi[4 * kk + 1], khi[4 * kk + 2], khi[4 * kk + 3], c0, c1);
                MMA(S[j], klo[4 * kk], klo[4 * kk + 1], klo[4 * kk + 2], klo[4 * kk + 3], b0, b1);
            }
        }
    }

    // ================= softmax on S fragments (registers) =================
    u32 phi[16], plo[16];
    {
        float m0 = -1e30f, m1 = -1e30f;
#pragma unroll
        for (int j = 0; j < 8; j++) {
            m0 = fmaxf(m0, fmaxf(S[j][0], S[j][1]));
            m1 = fmaxf(m1, fmaxf(S[j][2], S[j][3]));
        }
        m0 = fmaxf(m0, __shfl_xor_sync(0xffffffffu, m0, 1));
        m0 = fmaxf(m0, __shfl_xor_sync(0xffffffffu, m0, 2));
        m1 = fmaxf(m1, __shfl_xor_sync(0xffffffffu, m1, 1));
        m1 = fmaxf(m1, __shfl_xor_sync(0xffffffffu, m1, 2));
        float s0 = 0.f, s1 = 0.f;
#pragma unroll
        for (int j = 0; j < 8; j++) {
            S[j][0] = __expf(S[j][0] - m0); S[j][1] = __expf(S[j][1] - m0);
            S[j][2] = __expf(S[j][2] - m1); S[j][3] = __expf(S[j][3] - m1);
            s0 += S[j][0] + S[j][1];
            s1 += S[j][2] + S[j][3];
        }
        s0 += __shfl_xor_sync(0xffffffffu, s0, 1);
        s0 += __shfl_xor_sync(0xffffffffu, s0, 2);
        s1 += __shfl_xor_sync(0xffffffffu, s1, 1);
        s1 += __shfl_xor_sync(0xffffffffu, s1, 2);
        float i0 = 1.f / s0, i1 = 1.f / s1;
#pragma unroll
        for (int j = 0; j < 8; j++) {
            split2(S[j][0] * i0, S[j][1] * i0, phi[2 * j], plo[2 * j]);
            split2(S[j][2] * i1, S[j][3] * i1, phi[2 * j + 1], plo[2 * j + 1]);
        }
    }

    // ================= phase B: V proj + O = P V + gate =================
    for (int cc = 0; cc < 4; cc++) {
        float acc[8][4];
#pragma unroll
        for (int j = 0; j < 8; j++) { acc[j][0] = acc[j][1] = acc[j][2] = acc[j][3] = 0.f; }
        RUNHALF(acc, 0);
        RUNHALF(acc, 4);
        {   // V epilogue: +bias, split, transposed swizzled store Vt[c][256B]
            char* vth = smc + QH_B;
            char* vtl = smc + QL_B;
            const float* bias = bv + cc * 64;
            int vu0 = R >> 3;           // (R+qd)>>3, qd<8
            int q2 = qd * 2;
#pragma unroll
            for (int j = 0; j < 8; j++) {
                float2 bb = *(const float2*)(bias + 8 * j + tq * 2);
                int c0 = 8 * j + tq * 2;
                float f0 = acc[j][0] + bb.x, f1 = acc[j][1] + bb.y;
                float f2 = acc[j][2] + bb.x, f3 = acc[j][3] + bb.y;
                u32 a00 = (u32)(c0 * 256 + ((vu0 ^ (c0 & 7)) << 4) + q2);
                u32 a10 = (u32)((c0 + 1) * 256 + ((vu0 ^ ((c0 + 1) & 7)) << 4) + q2);
                u32 a01 = (u32)(c0 * 256 + (((vu0 + 1) ^ (c0 & 7)) << 4) + q2);
                u32 a11 = (u32)((c0 + 1) * 256 + (((vu0 + 1) ^ ((c0 + 1) & 7)) << 4) + q2);
                __nv_bfloat16 h;
                h = __float2bfloat16(f0); *(__nv_bfloat16*)(vth + a00) = h;
                *(__nv_bfloat16*)(vtl + a00) = __float2bfloat16(f0 - __bfloat162float(h));
                h = __float2bfloat16(f1); *(__nv_bfloat16*)(vth + a10) = h;
                *(__nv_bfloat16*)(vtl + a10) = __float2bfloat16(f1 - __bfloat162float(h));
                h = __float2bfloat16(f2); *(__nv_bfloat16*)(vth + a01) = h;
                *(__nv_bfloat16*)(vtl + a01) = __float2bfloat16(f2 - __bfloat162float(h));
                h = __float2bfloat16(f3); *(__nv_bfloat16*)(vth + a11) = h;
                *(__nv_bfloat16*)(vtl + a11) = __float2bfloat16(f3 - __bfloat162float(h));
            }
        }
        __syncthreads();
        // ---- O = P * Vc (A = P regs, B = Vt smem via ldmatrix) ----
        float O[8][4];
#pragma unroll
        for (int j = 0; j < 8; j++) { O[j][0] = O[j][1] = O[j][2] = O[j][3] = 0.f; }
#pragma unroll
        for (int kkv = 0; kkv < 4; kkv++) {
            u32 koff = (u32)(((kkv * 2) ^ txe) << 4);
#pragma unroll
            for (int j = 0; j < 8; j++) {
                u32 b0, b1, c0, c1;
                LDSM4(b0, b1, c0, c1, vAddrT + (u32)(j * 2048) + koff);
                MMA(O[j], phi[4 * kkv], phi[4 * kkv + 1], phi[4 * kkv + 2], phi[4 * kkv + 3], b0, b1);
                MMA(O[j], phi[4 * kkv], phi[4 * kkv + 1], phi[4 * kkv + 2], phi[4 * kkv + 3], c0, c1);
                MMA(O[j], plo[4 * kkv], plo[4 * kkv + 1], plo[4 * kkv + 2], plo[4 * kkv + 3], b0, b1);
            }
        }
        // ---- gate with x, store ----
        {
            int r0 = R + qd;
#pragma unroll
            for (int j = 0; j < 8; j++) {
                int col = cc * 64 + 8 * j + tq * 2;
                float2 x0 = *(const float2*)(xg + r0 * 256 + col);
                float2 x1 = *(const float2*)(xg + (r0 + 8) * 256 + col);
                float2 o0 = make_float2(O[j][0] * x0.x, O[j][1] * x0.y);
                float2 o1 = make_float2(O[j][2] * x1.x, O[j][3] * x1.y);
                *(float2*)(og + r0 * 256 + col) = o0;
                *(float2*)(og + (r0 + 8) * 256 + col) = o1;
            }
        }
        if (cc < 3) __syncthreads();   // Vt buffer reused next cc
    }
}

extern "C" void kernel_launch(void* const* d_in, const int* in_sizes, int n_in,
                              void* d_out, int out_size)
{
    const float* x  = (const float*)d_in[0];
    const float* wq = (const float*)d_in[1];
    const float* bq = (const float*)d_in[2];
    const float* wk = (const float*)d_in[3];
    const float* bk = (const float*)d_in[4];
    const float* wv = (const float*)d_in[5];
    const float* bv = (const float*)d_in[6];
    float* out = (float*)d_out;

    prep_w<<<768, 256>>>(wq, wk, wv);

    int n_bh = in_sizes[0] / 16384;   // B*H = 2048
    cudaFuncSetAttribute(attn_mma_kernel,
                         cudaFuncAttributeMaxDynamicSharedMemorySize, SMEM_B);
    attn_mma_kernel<<<n_bh / 2, 256, SMEM_B>>>(x, bq, bk, bv, out);
}

// round 15
// speedup vs baseline: 2.7142x; 1.0999x over previous
#include <cuda_runtime.h>
#include <cuda_bf16.h>
#include <cstdint>

typedef uint32_t u32;

// Pre-split transposed weights: Wt[n][k] bf16 hi/lo, row-major [256][256] (512B rows).
__device__ __align__(16) unsigned char g_Wh[3][131072];
__device__ __align__(16) unsigned char g_Wl[3][131072];

// ---- smem byte map (regions XOR-swizzled: 16B-unit col ^= (row & 7)) ----
#define XH_B   0             // X hi [128 rows][512B]
#define WB_B   65536         // 3 W buffers, each: hi[32][512B] + lo[32][512B] = 32K
#define WBUF_SZ 32768
#define QH_B   163840        // Q hi [128 rows][128B]   (phase B: Vt hi [64 rows][256B])
#define QL_B   180224        // Q lo
#define SMEM_B 196608

#define MMA(d, a0, a1, a2, a3, b0, b1) \
    asm volatile("mma.sync.aligned.m16n8k16.row.col.f32.bf16.bf16.f32 " \
        "{%0,%1,%2,%3},{%4,%5,%6,%7},{%8,%9},{%0,%1,%2,%3};" \
        : "+f"((d)[0]), "+f"((d)[1]), "+f"((d)[2]), "+f"((d)[3]) \
        : "r"(a0), "r"(a1), "r"(a2), "r"(a3), "r"(b0), "r"(b1))

#define LDSM4(r0, r1, r2, r3, a) \
    asm volatile("ldmatrix.sync.aligned.m8n8.x4.shared.b16 {%0,%1,%2,%3}, [%4];" \
        : "=r"(r0), "=r"(r1), "=r"(r2), "=r"(r3) : "r"(a))

#define CPA16(dst, src) \
    asm volatile("cp.async.cg.shared.global [%0], [%1], 16;" :: "r"(dst), "l"(src))
#define CPC()  asm volatile("cp.async.commit_group;")
#define CPW1() asm volatile("cp.async.wait_group 1;")

__device__ __forceinline__ void split2(float f0, float f1, u32& hp, u32& lp) {
    asm("cvt.rn.bf16x2.f32 %0, %1, %2;" : "=r"(hp) : "f"(f1), "f"(f0));
    float h0 = __uint_as_float(hp << 16);
    float h1 = __uint_as_float(hp & 0xffff0000u);
    asm("cvt.rn.bf16x2.f32 %0, %1, %2;" : "=r"(lp) : "f"(f1 - h1), "f"(f0 - h0));
}

// ---------------- prep: transpose + split weights ----------------
__global__ void prep_w(const float* __restrict__ wq, const float* __restrict__ wk,
                       const float* __restrict__ wv)
{
    int idx = blockIdx.x * blockDim.x + threadIdx.x;
    if (idx >= 3 * 65536) return;
    int w = idx >> 16, e = idx & 65535;
    int k = e >> 8, n = e & 255;
    const float* W = (w == 0) ? wq : (w == 1) ? wk : wv;
    float f = W[k * 256 + n];
    __nv_bfloat16 h = __float2bfloat16(f);
    __nv_bfloat16 l = __float2bfloat16(f - __bfloat162float(h));
    *(__nv_bfloat16*)(g_Wh[w] + n * 512 + k * 2) = h;   // Wt[n][k]
    *(__nv_bfloat16*)(g_Wl[w] + n * 512 + k * 2) = l;
}

// prefetch one half-chunk (32 n rows, hi+lo) into a W buffer, swizzled.
__device__ __forceinline__ void pf_half(int idx, u32 dst, int tid) {
    int wsel, row0;
    if (idx < 16) { wsel = (idx >> 1) & 1; row0 = (idx >> 2) * 64 + (idx & 1) * 32; }
    else { int j = idx - 16; wsel = 2; row0 = (j >> 1) * 64 + (j & 1) * 32; }
    const unsigned char* gh = g_Wh[wsel] + row0 * 512;
    const unsigned char* gl = g_Wl[wsel] + row0 * 512;
#pragma unroll
    for (int i = 0; i < 4; i++) {
        int e = tid + i * 256;               // 0..1023: 32 rows x 32 units
        int r = e >> 5, c = e & 31;
        u32 so = (u32)(r * 512 + ((c ^ (r & 7)) << 4));
        CPA16(dst + so, gh + r * 512 + c * 16);
        CPA16(dst + 16384 + so, gl + r * 512 + c * 16);
    }
    CPC();
}

// one half projection pass; single sync per stage; term-major MMA order.
#define RUNHALF(ACC, JB) do {                                                   \
    CPW1(); __syncthreads();                                                    \
    if (nextpf < 24) pf_half(nextpf, wbuf[nextpf % 3], tid); else CPC();        \
    nextpf++;                                                                   \
    u32 wbase = wAddrT + (u32)cur * WBUF_SZ;                                    \
    cur = (cur == 2) ? 0 : cur + 1;                                             \
    _Pragma("unroll")                                                           \
    for (int kk = 0; kk < 16; kk++) {                                           \
        u32 koff = (u32)(((kk * 2) ^ txe) << 4);                                \
        u32 ah0, ah1, ah2, ah3;                                                 \
        LDSM4(ah0, ah1, ah2, ah3, aXH + koff);                                  \
        u32 B0[4], B1[4], C0[4], C1[4];                                         \
        _Pragma("unroll")                                                       \
        for (int j = 0; j < 4; j++)                                             \
            LDSM4(B0[j], B1[j], C0[j], C1[j], wbase + (u32)(j * 4096) + koff);  \
        _Pragma("unroll")                                                       \
        for (int j = 0; j < 4; j++)                                             \
            MMA(ACC[(JB) + j], ah0, ah1, ah2, ah3, B0[j], B1[j]);               \
        _Pragma("unroll")                                                       \
        for (int j = 0; j < 4; j++)                                             \
            MMA(ACC[(JB) + j], alo[kk][0], alo[kk][1], alo[kk][2], alo[kk][3], B0[j], B1[j]); \
        _Pragma("unroll")                                                       \
        for (int j = 0; j < 4; j++)                                             \
            MMA(ACC[(JB) + j], ah0, ah1, ah2, ah3, C0[j], C1[j]);               \
    }                                                                           \
} while (0)

__global__ void __launch_bounds__(256, 1)
attn_mma_kernel(const float* __restrict__ x,
                const float* __restrict__ bq, const float* __restrict__ bk,
                const float* __restrict__ bv, float* __restrict__ out)
{
    extern __shared__ char smc[];
    u32 smb;
    asm("{ .reg .u64 t; cvta.to.shared.u64 t, %1; cvt.u32.u64 %0, t; }" : "=r"(smb) : "l"(smc));

    const int tid = threadIdx.x;
    const int w = tid >> 5, t = tid & 31;
    const int qd = t >> 2, tq = t & 3;
    const int R = w * 16;                 // warp's 16 stacked rows
    const int bh64 = (w >> 2) * 64;       // 0 (bh0) or 64 (bh1)

    // ldmatrix thread-role decomposition
    const int tm8 = t & 7;
    const int g8  = (t >> 3) & 1;
    const int g16 = t >> 4;
    const int txe = tm8 & 6, txo = tm8 & 1;

    const float* xg = x + (size_t)blockIdx.x * 32768;
    float*       og = out + (size_t)blockIdx.x * 32768;

    u32* qh = (u32*)(smc + QH_B);
    u32* ql = (u32*)(smc + QL_B);

    // ---- stage X: hi -> XH, lo -> WB region (temp), both swizzled ----
    {
        int row = tid >> 1, kh = (tid & 1) * 128;
        const float4* src = (const float4*)(xg + row * 256 + kh);
        int rx = row & 7;
        char* dh = smc + XH_B + row * 512;
        char* dl = smc + WB_B + row * 512;
#pragma unroll 8
        for (int j2 = 0; j2 < 32; j2++) {
            float4 v = src[j2];
            int unit = (kh >> 3) + (j2 >> 1);
            u32 off = (u32)(((unit ^ rx) << 4) + ((j2 & 1) << 3));
            u32 h0, l0, h1, l1;
            split2(v.x, v.y, h0, l0);
            split2(v.z, v.w, h1, l1);
            *(u32*)(dh + off) = h0; *(u32*)(dh + off + 4) = h1;
            *(u32*)(dl + off) = l0; *(u32*)(dl + off + 4) = l1;
        }
    }
    __syncthreads();

    // ---- A-lo fragments -> registers via ldmatrix (layout-identical to aXL path) ----
    const u32 aXH = smb + XH_B + (u32)(R + tm8 + 8 * g8) * 512 + (u32)((g16 ^ txo) << 4);
    u32 alo[16][4];
    {
        const u32 aXLt = smb + WB_B + (u32)(R + tm8 + 8 * g8) * 512 + (u32)((g16 ^ txo) << 4);
#pragma unroll
        for (int kk = 0; kk < 16; kk++) {
            u32 koff = (u32)(((kk * 2) ^ txe) << 4);
            LDSM4(alo[kk][0], alo[kk][1], alo[kk][2], alo[kk][3], aXLt + koff);
        }
    }
    __syncthreads();

    // ---- per-thread ldmatrix base addresses ----
    const u32 wAddrT = smb + WB_B + (u32)g16 * 16384 + (u32)tm8 * 512 + (u32)((g8 ^ txo) << 4);
    const u32 qAddrT = smb + QH_B + (u32)g16 * 16384 + (u32)(bh64 + tm8) * 128 + (u32)((g8 ^ txo) << 4);
    const u32 vAddrT = smb + QH_B + (u32)g16 * 16384 + (u32)tm8 * 256 + (u32)((bh64 >> 3) << 4) + (u32)((g8 ^ txo) << 4);

    // ---- prime the W pipeline (3 rotating buffers) ----
    u32 wbuf[3] = { smb + WB_B, smb + WB_B + WBUF_SZ, smb + WB_B + 2 * WBUF_SZ };
    pf_half(0, wbuf[0], tid);
    pf_half(1, wbuf[1], tid);
    int nextpf = 2, cur = 0;

    float S[8][4];
#pragma unroll
    for (int j = 0; j < 8; j++) { S[j][0] = S[j][1] = S[j][2] = S[j][3] = 0.f; }

    // ================= phase A: Q,K proj + S accumulation =================
    for (int cc = 0; cc < 4; cc++) {
        float acc[8][4];
        u32 khi[16], klo[16];
        // ---- Q projection ----
#pragma unroll
        for (int j = 0; j < 8; j++) { acc[j][0] = acc[j][1] = acc[j][2] = acc[j][3] = 0.f; }
        RUNHALF(acc, 0);
        RUNHALF(acc, 4);
        {   // Q epilogue: +bias, split, swizzled store [row][128B]
            const float* bias = bq + cc * 64;
            int r0 = R + qd;
#pragma unroll
            for (int j = 0; j < 8; j++) {
                float2 bb = *(const float2*)(bias + 8 * j + tq * 2);
                int wo = ((j ^ qd) << 2) + tq;
                u32 hp, lp;
                split2(acc[j][0] + bb.x, acc[j][1] + bb.y, hp, lp);
                qh[r0 * 32 + wo] = hp; ql[r0 * 32 + wo] = lp;
                split2(acc[j][2] + bb.x, acc[j][3] + bb.y, hp, lp);
                qh[(r0 + 8) * 32 + wo] = hp; ql[(r0 + 8) * 32 + wo] = lp;
            }
        }
        // ---- K projection (stays in registers) ----
#pragma unroll
        for (int j = 0; j < 8; j++) { acc[j][0] = acc[j][1] = acc[j][2] = acc[j][3] = 0.f; }
        RUNHALF(acc, 0);
        RUNHALF(acc, 4);
        {
            const float* bias = bk + cc * 64;
#pragma unroll
            for (int j = 0; j < 8; j++) {
                float2 bb = *(const float2*)(bias + 8 * j + tq * 2);
                split2(acc[j][0] + bb.x, acc[j][1] + bb.y, khi[2 * j], klo[2 * j]);
                split2(acc[j][2] + bb.x, acc[j][3] + bb.y, khi[2 * j + 1], klo[2 * j + 1]);
            }
        }
        // ---- S += Kc * Qc^T  (A = K regs, B = Q smem; term-major, groups of 4) ----
#pragma unroll
        for (int kk = 0; kk < 4; kk++) {
            u32 koff = (u32)(((kk * 2) ^ txe) << 4);
#pragma unroll
            for (int jg = 0; jg < 8; jg += 4) {
                u32 B0[4], B1[4], C0[4], C1[4];
#pragma unroll
                for (int j = 0; j < 4; j++)
                    LDSM4(B0[j], B1[j], C0[j], C1[j], qAddrT + (u32)((jg + j) * 1024) + koff);
#pragma unroll
                for (int j = 0; j < 4; j++)
                    MMA(S[jg + j], khi[4 * kk], khi[4 * kk + 1], khi[4 * kk + 2], khi[4 * kk + 3], B0[j], B1[j]);
#pragma unroll
                for (int j = 0; j < 4; j++)
                    MMA(S[jg + j], khi[4 * kk], khi[4 * kk + 1], khi[4 * kk + 2], khi[4 * kk + 3], C0[j], C1[j]);
#pragma unroll
                for (int j = 0; j < 4; j++)
                    MMA(S[jg + j], klo[4 * kk], klo[4 * kk + 1], klo[4 * kk + 2], klo[4 * kk + 3], B0[j], B1[j]);
            }
        }
    }

    // ================= softmax on S fragments (registers) =================
    u32 phi[16], plo[16];
    {
        float m0 = -1e30f, m1 = -1e30f;
#pragma unroll
        for (int j = 0; j < 8; j++) {
            m0 = fmaxf(m0, fmaxf(S[j][0], S[j][1]));
            m1 = fmaxf(m1, fmaxf(S[j][2], S[j][3]));
        }
        m0 = fmaxf(m0, __shfl_xor_sync(0xffffffffu, m0, 1));
        m0 = fmaxf(m0, __shfl_xor_sync(0xffffffffu, m0, 2));
        m1 = fmaxf(m1, __shfl_xor_sync(0xffffffffu, m1, 1));
        m1 = fmaxf(m1, __shfl_xor_sync(0xffffffffu, m1, 2));
        float s0 = 0.f, s1 = 0.f;
#pragma unroll
        for (int j = 0; j < 8; j++) {
            S[j][0] = __expf(S[j][0] - m0); S[j][1] = __expf(S[j][1] - m0);
            S[j][2] = __expf(S[j][2] - m1); S[j][3] = __expf(S[j][3] - m1);
            s0 += S[j][0] + S[j][1];
            s1 += S[j][2] + S[j][3];
        }
        s0 += __shfl_xor_sync(0xffffffffu, s0, 1);
        s0 += __shfl_xor_sync(0xffffffffu, s0, 2);
        s1 += __shfl_xor_sync(0xffffffffu, s1, 1);
        s1 += __shfl_xor_sync(0xffffffffu, s1, 2);
        float i0 = 1.f / s0, i1 = 1.f / s1;
#pragma unroll
        for (int j = 0; j < 8; j++) {
            split2(S[j][0] * i0, S[j][1] * i0, phi[2 * j], plo[2 * j]);
            split2(S[j][2] * i1, S[j][3] * i1, phi[2 * j + 1], plo[2 * j + 1]);
        }
    }

    // ================= phase B: V proj + O = P V + gate =================
    for (int cc = 0; cc < 4; cc++) {
        float acc[8][4];
#pragma unroll
        for (int j = 0; j < 8; j++) { acc[j][0] = acc[j][1] = acc[j][2] = acc[j][3] = 0.f; }
        RUNHALF(acc, 0);
        RUNHALF(acc, 4);
        {   // V epilogue: +bias, split, transposed swizzled store Vt[c][256B]
            char* vth = smc + QH_B;
            char* vtl = smc + QL_B;
            const float* bias = bv + cc * 64;
            int vu0 = R >> 3;
            int q2 = qd * 2;
#pragma unroll
            for (int j = 0; j < 8; j++) {
                float2 bb = *(const float2*)(bias + 8 * j + tq * 2);
                int c0 = 8 * j + tq * 2;
                float f0 = acc[j][0] + bb.x, f1 = acc[j][1] + bb.y;
                float f2 = acc[j][2] + bb.x, f3 = acc[j][3] + bb.y;
                u32 a00 = (u32)(c0 * 256 + ((vu0 ^ (c0 & 7)) << 4) + q2);
                u32 a10 = (u32)((c0 + 1) * 256 + ((vu0 ^ ((c0 + 1) & 7)) << 4) + q2);
                u32 a01 = (u32)(c0 * 256 + (((vu0 + 1) ^ (c0 & 7)) << 4) + q2);
                u32 a11 = (u32)((c0 + 1) * 256 + (((vu0 + 1) ^ ((c0 + 1) & 7)) << 4) + q2);
                __nv_bfloat16 h;
                h = __float2bfloat16(f0); *(__nv_bfloat16*)(vth + a00) = h;
                *(__nv_bfloat16*)(vtl + a00) = __float2bfloat16(f0 - __bfloat162float(h));
                h = __float2bfloat16(f1); *(__nv_bfloat16*)(vth + a10) = h;
                *(__nv_bfloat16*)(vtl + a10) = __float2bfloat16(f1 - __bfloat162float(h));
                h = __float2bfloat16(f2); *(__nv_bfloat16*)(vth + a01) = h;
                *(__nv_bfloat16*)(vtl + a01) = __float2bfloat16(f2 - __bfloat162float(h));
                h = __float2bfloat16(f3); *(__nv_bfloat16*)(vth + a11) = h;
                *(__nv_bfloat16*)(vtl + a11) = __float2bfloat16(f3 - __bfloat162float(h));
            }
        }
        __syncthreads();
        // ---- O = P * Vc (A = P regs, B = Vt smem; term-major, groups of 4) ----
        float O[8][4];
#pragma unroll
        for (int j = 0; j < 8; j++) { O[j][0] = O[j][1] = O[j][2] = O[j][3] = 0.f; }
#pragma unroll
        for (int kkv = 0; kkv < 4; kkv++) {
            u32 koff = (u32)(((kkv * 2) ^ txe) << 4);
#pragma unroll
            for (int jg = 0; jg < 8; jg += 4) {
                u32 B0[4], B1[4], C0[4], C1[4];
#pragma unroll
                for (int j = 0; j < 4; j++)
                    LDSM4(B0[j], B1[j], C0[j], C1[j], vAddrT + (u32)((jg + j) * 2048) + koff);
#pragma unroll
                for (int j = 0; j < 4; j++)
                    MMA(O[jg + j], phi[4 * kkv], phi[4 * kkv + 1], phi[4 * kkv + 2], phi[4 * kkv + 3], B0[j], B1[j]);
#pragma unroll
                for (int j = 0; j < 4; j++)
                    MMA(O[jg + j], phi[4 * kkv], phi[4 * kkv + 1], phi[4 * kkv + 2], phi[4 * kkv + 3], C0[j], C1[j]);
#pragma unroll
                for (int j = 0; j < 4; j++)
                    MMA(O[jg + j], plo[4 * kkv], plo[4 * kkv + 1], plo[4 * kkv + 2], plo[4 * kkv + 3], B0[j], B1[j]);
            }
        }
        // ---- gate with x, store ----
        {
            int r0 = R + qd;
#pragma unroll
            for (int j = 0; j < 8; j++) {
                int col = cc * 64 + 8 * j + tq * 2;
                float2 x0 = *(const float2*)(xg + r0 * 256 + col);
                float2 x1 = *(const float2*)(xg + (r0 + 8) * 256 + col);
                float2 o0 = make_float2(O[j][0] * x0.x, O[j][1] * x0.y);
                float2 o1 = make_float2(O[j][2] * x1.x, O[j][3] * x1.y);
                *(float2*)(og + r0 * 256 + col) = o0;
                *(float2*)(og + (r0 + 8) * 256 + col) = o1;
            }
        }
    }
}

extern "C" void kernel_launch(void* const* d_in, const int* in_sizes, int n_in,
                              void* d_out, int out_size)
{
    const float* x  = (const float*)d_in[0];
    const float* wq = (const float*)d_in[1];
    const float* bq = (const float*)d_in[2];
    const float* wk = (const float*)d_in[3];
    const float* bk = (const float*)d_in[4];
    const float* wv = (const float*)d_in[5];
    const float* bv = (const float*)d_in[6];
    float* out = (float*)d_out;

    prep_w<<<768, 256>>>(wq, wk, wv);

    int n_bh = in_sizes[0] / 16384;   // B*H = 2048
    cudaFuncSetAttribute(attn_mma_kernel,
                         cudaFuncAttributeMaxDynamicSharedMemorySize, SMEM_B);
    attn_mma_kernel<<<n_bh / 2, 256, SMEM_B>>>(x, bq, bk, bv, out);
}